// round 7
// baseline (speedup 1.0000x reference)
#include <cuda_runtime.h>
#include <cstdint>
#include <cstddef>

// Problem constants
#define BDIM 4096
#define TDIM 168
#define IDIM 19
#define HDIM 64
#define GDIM 256          // 4*H
#define RPT  7            // rows per rg-group
#define RPC  28           // rows per CTA
#define NCTA 147
#define NT   256

// 704 MB scratch: zx0[t][b][hu][gi]  (layer-0 input projection + biases)
__device__ float g_zx[(size_t)TDIM * BDIM * GDIM];

// ---------------- f32x2 packed-math helpers (sm_100+) ----------------
__device__ __forceinline__ void fma2(unsigned long long& d,
                                     unsigned long long a,
                                     unsigned long long b) {
    asm("fma.rn.f32x2 %0, %1, %2, %0;" : "+l"(d) : "l"(a), "l"(b));
}
__device__ __forceinline__ unsigned long long pack2(float lo, float hi) {
    unsigned long long r;
    asm("mov.b64 %0, {%1, %2};" : "=l"(r) : "f"(lo), "f"(hi));
    return r;
}
__device__ __forceinline__ float redu2(unsigned long long v) {
    float lo, hi;
    asm("mov.b64 {%0, %1}, %2;" : "=f"(lo), "=f"(hi) : "l"(v));
    return lo + hi;
}
__device__ __forceinline__ unsigned long long ld64(const float* p) {
    return *reinterpret_cast<const unsigned long long*>(p);
}

// ---------------- fast activations ----------------
__device__ __forceinline__ float ex2f(float x) {
    float y; asm("ex2.approx.f32 %0, %1;" : "=f"(y) : "f"(x)); return y;
}
__device__ __forceinline__ float rcpf(float x) {
    float y; asm("rcp.approx.f32 %0, %1;" : "=f"(y) : "f"(x)); return y;
}
#define LOG2E 1.4426950408889634f
__device__ __forceinline__ float sigmoidf_(float x) {
    return rcpf(1.0f + ex2f(-x * LOG2E));
}
__device__ __forceinline__ float tanhf_(float x) {
    return 1.0f - 2.0f * rcpf(ex2f(2.0f * LOG2E * x) + 1.0f);
}

// ---------------- named barrier ----------------
__device__ __forceinline__ void barn(int id, int cnt) {
    asm volatile("bar.sync %0, %1;" :: "r"(id), "r"(cnt) : "memory");
}

// =====================================================================
// Prep kernel: g_zx[t][b][hu][gi] = x(b,t,:) . Wih0 + bih0 + bhh0
// =====================================================================
#define TB 4
#define BB 32
#define PNT 256
__global__ void __launch_bounds__(PNT) prep_kernel(
    const float* __restrict__ x,
    const float* __restrict__ Wih0,
    const float* __restrict__ bih0,
    const float* __restrict__ bhh0)
{
    __shared__ __align__(16) float sW[IDIM * GDIM];
    __shared__ float sX[TB][BB][IDIM + 1];
    const int tid = threadIdx.x;
    const int t0 = blockIdx.x * TB;
    const int b0 = blockIdx.y * BB;

    for (int idx = tid; idx < IDIM * GDIM; idx += PNT) {
        int i  = idx >> 8;
        int c  = idx & 255;
        int hh = c >> 2, gi = c & 3;
        sW[idx] = Wih0[(gi * HDIM + hh) * IDIM + i];
    }
    for (int idx = tid; idx < TB * BB * IDIM; idx += PNT) {
        int i  = idx % IDIM;
        int rb = idx / IDIM;
        int bb = rb % BB, tt = rb / BB;
        sX[tt][bb][i] = x[((size_t)(b0 + bb) * TDIM + (t0 + tt)) * IDIM + i];
    }
    __syncthreads();

    const int hh = tid & 63;
    const int sub = tid >> 6;
    float bias[4];
#pragma unroll
    for (int gi = 0; gi < 4; gi++)
        bias[gi] = bih0[gi * HDIM + hh] + bhh0[gi * HDIM + hh];
    const unsigned long long b01 = pack2(bias[0], bias[1]);
    const unsigned long long b23 = pack2(bias[2], bias[3]);

    for (int tt = 0; tt < TB; tt++) {
#pragma unroll
        for (int j = 0; j < BB / 4; j++) {
            const int bb = sub * (BB / 4) + j;
            unsigned long long a01 = b01, a23 = b23;
#pragma unroll
            for (int i = 0; i < IDIM; i++) {
                float xv = sX[tt][bb][i];
                unsigned long long xp = pack2(xv, xv);
                const float* wp = &sW[i * GDIM + hh * 4];
                fma2(a01, xp, ld64(wp));
                fma2(a23, xp, ld64(wp + 2));
            }
            float r0, r1, r2, r3;
            asm("mov.b64 {%0, %1}, %2;" : "=f"(r0), "=f"(r1) : "l"(a01));
            asm("mov.b64 {%0, %1}, %2;" : "=f"(r2), "=f"(r3) : "l"(a23));
            float4 out4 = make_float4(r0, r1, r2, r3);
            *reinterpret_cast<float4*>(
                &g_zx[(((size_t)(t0 + tt) * BDIM + (b0 + bb)) * HDIM + hh) * 4]) = out4;
        }
    }
}

// =====================================================================
// Main recurrent kernel: 147 CTAs x 256 threads, 28 rows per CTA.
// Thread: hu = tid&63, rg = tid>>6; 7 rows x 4 gates per thread.
// NEW vs R5: groups 2,3 start the timestep loop with a ~5600-cycle skew.
// SMSP k hosts one warp of groups {0,1} and one of groups {2,3}; with no
// cross-group sync inside the loop the skew persists, anti-phasing the
// two warps so one warp's MUFU/activation/LDS-latency windows overlap the
// other's FMA phase (phase-locked warps were the 42% idle source).
// =====================================================================
__global__ void __launch_bounds__(NT, 1) lstm_kernel(
    const float* __restrict__ Whh0,
    const float* __restrict__ Wih1,
    const float* __restrict__ Whh1,
    const float* __restrict__ bih1,
    const float* __restrict__ bhh1,
    const float* __restrict__ Wfc,
    const float* __restrict__ bfc,
    float* __restrict__ out)
{
    extern __shared__ __align__(16) float smem[];
    float* sW0 = smem;                         // 16*256*4 = 16384 floats (64 KB)
    float* sW1 = sW0 + 16 * GDIM * 4;          // 32*256*4 = 32768 floats (128 KB)
    float* h0a = sW1 + 32 * GDIM * 4;          // 28*64
    float* h0b = h0a + RPC * HDIM;
    float* h1a = h0b + RPC * HDIM;
    float* h1b = h1a + RPC * HDIM;

    const int tid = threadIdx.x;
    const int hu  = tid & 63;
    const int rg  = tid >> 6;                  // 0..3
    const int rbase = rg * RPT;
    const size_t growbase = (size_t)blockIdx.x * RPC + rbase;
    const int bid = 1 + rg;                    // named barrier per rg-group

    // ---- stage weights in [kkk][g][4] layout (coalesced float4 gmem reads) ----
    for (int idx = tid; idx < GDIM * 16; idx += NT) {
        int g = idx & 255, kkk = idx >> 8;
        *reinterpret_cast<float4*>(&sW0[(kkk * GDIM + g) * 4]) =
            *reinterpret_cast<const float4*>(&Whh0[g * HDIM + kkk * 4]);
    }
    for (int idx = tid; idx < GDIM * 32; idx += NT) {
        int g = idx & 255, kkk = idx >> 8;
        const float* src = (kkk < 16) ? &Wih1[g * HDIM + kkk * 4]
                                      : &Whh1[g * HDIM + (kkk - 16) * 4];
        *reinterpret_cast<float4*>(&sW1[(kkk * GDIM + g) * 4]) =
            *reinterpret_cast<const float4*>(src);
    }
    for (int idx = tid; idx < RPC * HDIM; idx += NT) {
        h0a[idx] = 0.0f; h0b[idx] = 0.0f;
        h1a[idx] = 0.0f; h1b[idx] = 0.0f;
    }

    float b1v[4];
#pragma unroll
    for (int gi = 0; gi < 4; gi++)
        b1v[gi] = bih1[gi * HDIM + hu] + bhh1[gi * HDIM + hu];

    float c0[RPT], c1[RPT];
#pragma unroll
    for (int r = 0; r < RPT; r++) { c0[r] = 0.0f; c1[r] = 0.0f; }

    __syncthreads();   // weights + initial h visible to all

    // ---- one-time skew for groups 2,3: dependent FFMA chain (~5600 cyc) ----
    if (rg >= 2) {
        float a = (float)(tid + 1);
#pragma unroll 1
        for (int i = 0; i < 1400; i++)
            asm volatile("fma.rn.f32 %0, %0, 0f3F800001, 0f2F800000;" : "+f"(a));
        // impossible side effect keeps the chain live without perturbing state
        if (a == 0.0f) h0a[tid & 7] += a;
    }

    // GEMM over one kkk slice (4 consecutive k): 4 gates x 7 rows,
    // both operands via LDS.128.
#define GEMM_KKK(SW, HS, KKK, HOFF)                                              \
    do {                                                                         \
        ulonglong2 hv[RPT];                                                      \
        _Pragma("unroll")                                                        \
        for (int r = 0; r < RPT; r++)                                            \
            hv[r] = *reinterpret_cast<const ulonglong2*>(                        \
                &HS[(rbase + r) * HDIM + (HOFF)]);                               \
        _Pragma("unroll")                                                        \
        for (int gi = 0; gi < 4; gi++) {                                         \
            ulonglong2 wv = *reinterpret_cast<const ulonglong2*>(                \
                &SW[((KKK) * GDIM + gi * 64 + hu) * 4]);                         \
            _Pragma("unroll")                                                    \
            for (int r = 0; r < RPT; r++) {                                      \
                fma2(acc[r][gi], hv[r].x, wv.x);                                 \
                fma2(acc[r][gi], hv[r].y, wv.y);                                 \
            }                                                                    \
        }                                                                        \
    } while (0)

    float* h0r = h0a; float* h0w = h0b;
    float* h1r = h1a; float* h1w = h1b;

    for (int t = 0; t < TDIM; t++) {
        unsigned long long acc[RPT][4];

        // ================= layer 0 =================
        float4 zx[RPT];
#pragma unroll
        for (int r = 0; r < RPT; r++) {
            size_t grow = growbase + r;
            zx[r] = (grow < BDIM)
                ? *reinterpret_cast<const float4*>(
                      &g_zx[(((size_t)t * BDIM + grow) * HDIM + hu) * 4])
                : make_float4(0.f, 0.f, 0.f, 0.f);
        }

#pragma unroll
        for (int r = 0; r < RPT; r++)
#pragma unroll
            for (int gi = 0; gi < 4; gi++) acc[r][gi] = 0ULL;
#pragma unroll 2
        for (int kkk = 0; kkk < 16; kkk++)
            GEMM_KKK(sW0, h0r, kkk, kkk * 4);

#pragma unroll
        for (int r = 0; r < RPT; r++) {
            float zi = redu2(acc[r][0]) + zx[r].x;
            float zf = redu2(acc[r][1]) + zx[r].y;
            float zg = redu2(acc[r][2]) + zx[r].z;
            float zo = redu2(acc[r][3]) + zx[r].w;
            float ig = sigmoidf_(zi);
            float fg = sigmoidf_(zf);
            float gg = tanhf_(zg);
            float og = sigmoidf_(zo);
            float c = fg * c0[r] + ig * gg;
            c0[r] = c;
            h0w[(rbase + r) * HDIM + hu] = og * tanhf_(c);
        }
        barn(bid, 64);       // group-local: h0w visible (write buffer != read)

        // ================= layer 1 (K=128: [h0_new ; h1_old]) =================
#pragma unroll
        for (int r = 0; r < RPT; r++)
#pragma unroll
            for (int gi = 0; gi < 4; gi++) acc[r][gi] = 0ULL;
#pragma unroll 2
        for (int kkk = 0; kkk < 16; kkk++)
            GEMM_KKK(sW1, h0w, kkk, kkk * 4);
#pragma unroll 2
        for (int kkk = 16; kkk < 32; kkk++)
            GEMM_KKK(sW1, h1r, kkk, (kkk - 16) * 4);

#pragma unroll
        for (int r = 0; r < RPT; r++) {
            float zi = redu2(acc[r][0]) + b1v[0];
            float zf = redu2(acc[r][1]) + b1v[1];
            float zg = redu2(acc[r][2]) + b1v[2];
            float zo = redu2(acc[r][3]) + b1v[3];
            float ig = sigmoidf_(zi);
            float fg = sigmoidf_(zf);
            float gg = tanhf_(zg);
            float og = sigmoidf_(zo);
            float c = fg * c1[r] + ig * gg;
            c1[r] = c;
            h1w[(rbase + r) * HDIM + hu] = og * tanhf_(c);
        }
        barn(bid, 64);       // group-local: h1w visible; safe to swap

        // swap double buffers
        float* tp;
        tp = h0r; h0r = h0w; h0w = tp;
        tp = h1r; h1r = h1w; h1w = tp;
    }

    __syncthreads();

    // ---- final FC on last hidden state (h1r holds the last write) ----
    if (tid < RPC) {
        size_t grow = (size_t)blockIdx.x * RPC + tid;
        if (grow < BDIM) {
            float s = bfc[0];
#pragma unroll 8
            for (int k = 0; k < HDIM; k++) s += h1r[tid * HDIM + k] * Wfc[k];
            out[grow] = s;
        }
    }
}

// =====================================================================
extern "C" void kernel_launch(void* const* d_in, const int* in_sizes, int n_in,
                              void* d_out, int out_size)
{
    const float* x    = (const float*)d_in[0];
    const float* Wih0 = (const float*)d_in[1];
    const float* Whh0 = (const float*)d_in[2];
    const float* bih0 = (const float*)d_in[3];
    const float* bhh0 = (const float*)d_in[4];
    const float* Wih1 = (const float*)d_in[5];
    const float* Whh1 = (const float*)d_in[6];
    const float* bih1 = (const float*)d_in[7];
    const float* bhh1 = (const float*)d_in[8];
    const float* Wfc  = (const float*)d_in[9];
    const float* bfc  = (const float*)d_in[10];
    float* out = (float*)d_out;

    const int smem_bytes = (16 * GDIM * 4 + 32 * GDIM * 4 + 4 * RPC * HDIM) * 4;
    cudaFuncSetAttribute(lstm_kernel,
                         cudaFuncAttributeMaxDynamicSharedMemorySize, smem_bytes);

    dim3 pgrid(TDIM / TB, BDIM / BB);
    prep_kernel<<<pgrid, PNT>>>(x, Wih0, bih0, bhh0);
    lstm_kernel<<<NCTA, NT, smem_bytes>>>(Whh0, Wih1, Whh1, bih1, bhh1,
                                          Wfc, bfc, out);
}

// round 8
// speedup vs baseline: 1.5646x; 1.5646x over previous
#include <cuda_runtime.h>
#include <cuda_fp16.h>
#include <cstdint>
#include <cstddef>

// Problem constants
#define BDIM 4096
#define TDIM 168
#define IDIM 19
#define HDIM 64
#define GDIM 256          // 4*H
#define MROWS 32          // rows per CTA
#define LCTA 128          // lstm CTAs (128*32 = 4096)
#define NT   256

// 352 MB scratch: zx0[t][b][col] fp16, col = hu*4 + gate_type
__device__ __half g_zx[(size_t)TDIM * BDIM * GDIM];

// ---------------- f32x2 helpers (prep kernel) ----------------
__device__ __forceinline__ void fma2(unsigned long long& d,
                                     unsigned long long a,
                                     unsigned long long b) {
    asm("fma.rn.f32x2 %0, %1, %2, %0;" : "+l"(d) : "l"(a), "l"(b));
}
__device__ __forceinline__ unsigned long long pack2(float lo, float hi) {
    unsigned long long r;
    asm("mov.b64 %0, {%1, %2};" : "=l"(r) : "f"(lo), "f"(hi));
    return r;
}
__device__ __forceinline__ unsigned long long ld64(const float* p) {
    return *reinterpret_cast<const unsigned long long*>(p);
}

// ---------------- fast activations ----------------
__device__ __forceinline__ float ex2f(float x) {
    float y; asm("ex2.approx.f32 %0, %1;" : "=f"(y) : "f"(x)); return y;
}
__device__ __forceinline__ float rcpf(float x) {
    float y; asm("rcp.approx.f32 %0, %1;" : "=f"(y) : "f"(x)); return y;
}
#define L2E 1.4426950408889634f
// b + c / (1 + 2^(a*z)) :  sigmoid = (-L2E, 0, 1) ; tanh = (2*L2E, 1, -2)
__device__ __forceinline__ float actv(float z, float a, float b, float c) {
    return fmaf(c, rcpf(1.0f + ex2f(a * z)), b);
}

// ---------------- smem half-pair access with SW128-style XOR swizzle ------
// rows are 64 halves = 128B; chunk bits [6:4] ^= row&7 -> conflict-free
__device__ __forceinline__ uint32_t lds_hp(const __half* base, int row, int k) {
    int off = row * 128 + k * 2;
    off ^= (off >> 3) & 0x70;
    return *reinterpret_cast<const uint32_t*>(
        reinterpret_cast<const char*>(base) + off);
}
__device__ __forceinline__ void sts_h(__half* base, int row, int k, __half v) {
    int off = row * 128 + k * 2;
    off ^= (off >> 3) & 0x70;
    *reinterpret_cast<__half*>(reinterpret_cast<char*>(base) + off) = v;
}

// ---------------- mma m16n8k16 f16 -> f32 ----------------
__device__ __forceinline__ void mma16816(float* d, const uint32_t* a,
                                         const uint32_t* b) {
    asm volatile(
        "mma.sync.aligned.m16n8k16.row.col.f32.f16.f16.f32 "
        "{%0,%1,%2,%3},{%4,%5,%6,%7},{%8,%9},{%0,%1,%2,%3};"
        : "+f"(d[0]), "+f"(d[1]), "+f"(d[2]), "+f"(d[3])
        : "r"(a[0]), "r"(a[1]), "r"(a[2]), "r"(a[3]), "r"(b[0]), "r"(b[1]));
}

// =====================================================================
// Prep kernel: g_zx[t][b][hu*4+gi] = x(b,t,:).Wih0 + bih0 + bhh0  (fp16 out)
// =====================================================================
#define TB 4
#define BB 32
#define PNT 256
__global__ void __launch_bounds__(PNT) prep_kernel(
    const float* __restrict__ x,
    const float* __restrict__ Wih0,
    const float* __restrict__ bih0,
    const float* __restrict__ bhh0)
{
    __shared__ __align__(16) float sW[IDIM * GDIM];
    __shared__ float sX[TB][BB][IDIM + 1];
    const int tid = threadIdx.x;
    const int t0 = blockIdx.x * TB;
    const int b0 = blockIdx.y * BB;

    for (int idx = tid; idx < IDIM * GDIM; idx += PNT) {
        int i  = idx >> 8;
        int c  = idx & 255;
        int hh = c >> 2, gi = c & 3;
        sW[idx] = Wih0[(gi * HDIM + hh) * IDIM + i];
    }
    for (int idx = tid; idx < TB * BB * IDIM; idx += PNT) {
        int i  = idx % IDIM;
        int rb = idx / IDIM;
        int bb = rb % BB, tt = rb / BB;
        sX[tt][bb][i] = x[((size_t)(b0 + bb) * TDIM + (t0 + tt)) * IDIM + i];
    }
    __syncthreads();

    const int hh = tid & 63;
    const int sub = tid >> 6;
    float bias[4];
#pragma unroll
    for (int gi = 0; gi < 4; gi++)
        bias[gi] = bih0[gi * HDIM + hh] + bhh0[gi * HDIM + hh];
    const unsigned long long b01 = pack2(bias[0], bias[1]);
    const unsigned long long b23 = pack2(bias[2], bias[3]);

    for (int tt = 0; tt < TB; tt++) {
#pragma unroll
        for (int j = 0; j < BB / 4; j++) {
            const int bb = sub * (BB / 4) + j;
            unsigned long long a01 = b01, a23 = b23;
#pragma unroll
            for (int i = 0; i < IDIM; i++) {
                float xv = sX[tt][bb][i];
                unsigned long long xp = pack2(xv, xv);
                const float* wp = &sW[i * GDIM + hh * 4];
                fma2(a01, xp, ld64(wp));
                fma2(a23, xp, ld64(wp + 2));
            }
            float r0, r1, r2, r3;
            asm("mov.b64 {%0, %1}, %2;" : "=f"(r0), "=f"(r1) : "l"(a01));
            asm("mov.b64 {%0, %1}, %2;" : "=f"(r2), "=f"(r3) : "l"(a23));
            __half2 h01 = __floats2half2_rn(r0, r1);
            __half2 h23 = __floats2half2_rn(r2, r3);
            uint2 o;
            o.x = *reinterpret_cast<uint32_t*>(&h01);
            o.y = *reinterpret_cast<uint32_t*>(&h23);
            *reinterpret_cast<uint2*>(
                &g_zx[(((size_t)(t0 + tt) * BDIM + (b0 + bb)) * HDIM + hh) * 4]) = o;
        }
    }
}

// =====================================================================
// LSTM kernel: 128 CTAs x 256 threads, 32 rows per CTA, fp16 HMMA.
//  - gate columns reordered col = hu*4 + ty (matches g_zx layout)
//  - warp w owns cols [32w, 32w+32); ALL weights live in B-fragment regs
//  - h kept fp16 in swizzled smem, double-buffered per layer
//  - D-frag thread pairing: lane even (E) holds (i,f), lane^1 (O) holds
//    (g,o) of the same hu -> 2 shfl.xor(1) per tile for the cell update
// =====================================================================
__global__ void __launch_bounds__(NT, 1) lstm_kernel(
    const float* __restrict__ Whh0,
    const float* __restrict__ Wih1,
    const float* __restrict__ Whh1,
    const float* __restrict__ bih1,
    const float* __restrict__ bhh1,
    const float* __restrict__ Wfc,
    const float* __restrict__ bfc,
    float* __restrict__ out)
{
    extern __shared__ __align__(16) __half smem[];
    __half* sW0  = smem;                 // 256 x 64 halves (32 KB)
    __half* sW1a = sW0 + 256 * 64;       // Wih1 (32 KB)
    __half* sW1b = sW1a + 256 * 64;      // Whh1 (32 KB)
    __half* h0buf[2] = { sW1b + 256 * 64,            sW1b + 256 * 64 + 2048 };
    __half* h1buf[2] = { sW1b + 256 * 64 + 4096,     sW1b + 256 * 64 + 6144 };

    const int tid  = threadIdx.x;
    const int w    = tid >> 5;           // warp 0..7
    const int lane = tid & 31;
    const int lrow = lane >> 2;          // 0..7
    const int lq   = lane & 3;           // 0..3
    const bool isE = (lane & 1) == 0;

    // ---- stage weights fp32 -> fp16, column order col = hu*4+ty ----
    for (int idx = tid; idx < 256 * 64; idx += NT) {
        int n = idx >> 6, k = idx & 63;
        int hu = n >> 2, ty = n & 3;
        int g = ty * HDIM + hu;
        sts_h(sW0,  n, k, __float2half_rn(Whh0[g * HDIM + k]));
        sts_h(sW1a, n, k, __float2half_rn(Wih1[g * HDIM + k]));
        sts_h(sW1b, n, k, __float2half_rn(Whh1[g * HDIM + k]));
    }
    for (int idx = tid; idx < 2048; idx += NT) {
        h0buf[0][idx] = __half(0.0f); h0buf[1][idx] = __half(0.0f);
        h1buf[0][idx] = __half(0.0f); h1buf[1][idx] = __half(0.0f);
    }
    __syncthreads();

    // ---- preload ALL B fragments into registers (one-time) ----
    // Bw[g][nt][kt][2]: g=0:L0(Whh0), 1:L1a(Wih1), 2:L1b(Whh1)
    uint32_t Bw[3][4][4][2];
#pragma unroll
    for (int nt = 0; nt < 4; nt++) {
        int n = w * 32 + nt * 8 + lrow;
#pragma unroll
        for (int kt = 0; kt < 4; kt++) {
            int k = kt * 16 + 2 * lq;
            Bw[0][nt][kt][0] = lds_hp(sW0,  n, k);
            Bw[0][nt][kt][1] = lds_hp(sW0,  n, k + 8);
            Bw[1][nt][kt][0] = lds_hp(sW1a, n, k);
            Bw[1][nt][kt][1] = lds_hp(sW1a, n, k + 8);
            Bw[2][nt][kt][0] = lds_hp(sW1b, n, k);
            Bw[2][nt][kt][1] = lds_hp(sW1b, n, k + 8);
        }
    }

    // ---- L1 biases for my 8 columns ----
    float bias1[4][2];
#pragma unroll
    for (int nt = 0; nt < 4; nt++)
#pragma unroll
        for (int cc = 0; cc < 2; cc++) {
            int gcol = w * 32 + nt * 8 + 2 * lq + cc;
            int g = (gcol & 3) * HDIM + (gcol >> 2);
            bias1[nt][cc] = bih1[g] + bhh1[g];
        }

    // activation constants for my col-0 slot (E: sigmoid, O: tanh)
    const float aA = isE ? -L2E : 2.0f * L2E;
    const float bA = isE ? 0.0f : 1.0f;
    const float cA = isE ? 1.0f : -2.0f;

    // cell states (E lanes own them): index (mt*4+nt)*2 + rowhalf
    float cs0[16], cs1[16];
#pragma unroll
    for (int i = 0; i < 16; i++) { cs0[i] = 0.0f; cs1[i] = 0.0f; }

    // per-thread zx base (halves): row = cta*32 + lrow, col = w*32 + 2*lq
    const __half* zbase = g_zx +
        ((size_t)(blockIdx.x * MROWS + lrow) * GDIM + w * 32 + 2 * lq);

    // O-lane h column (global k within CTA's h row)
    // gcol(cc=0) = w*32 + nt*8 + 2*lq -> hu = gcol>>2 = w*8 + 2*nt + (lq==3)
    const int huO0 = w * 8 + ((lq == 3) ? 1 : 0);

    int pp = 0;   // read buffer index

#define GEMM_ACC(HB, BW)                                                        \
    do {                                                                        \
        _Pragma("unroll")                                                       \
        for (int mt = 0; mt < 2; mt++) {                                        \
            _Pragma("unroll")                                                   \
            for (int kt = 0; kt < 4; kt++) {                                    \
                uint32_t a[4];                                                  \
                int m = mt * 16 + lrow;                                         \
                int k = kt * 16 + 2 * lq;                                       \
                a[0] = lds_hp(HB, m,     k);                                    \
                a[1] = lds_hp(HB, m + 8, k);                                    \
                a[2] = lds_hp(HB, m,     k + 8);                                \
                a[3] = lds_hp(HB, m + 8, k + 8);                                \
                _Pragma("unroll")                                               \
                for (int nt = 0; nt < 4; nt++)                                  \
                    mma16816(d[mt][nt], a, BW[nt][kt]);                         \
            }                                                                   \
        }                                                                       \
    } while (0)

#define CELL(CS, HW)                                                            \
    do {                                                                        \
        _Pragma("unroll")                                                       \
        for (int mt = 0; mt < 2; mt++) {                                        \
            _Pragma("unroll")                                                   \
            for (int nt = 0; nt < 4; nt++) {                                    \
                float* dd = d[mt][nt];                                          \
                float v0 = actv(dd[0], aA, bA, cA);     /* E:si  O:tg  */       \
                float v1 = actv(dd[1], -L2E, 0.f, 1.f); /* E:sf  O:so  */       \
                float v2 = actv(dd[2], aA, bA, cA);                             \
                float v3 = actv(dd[3], -L2E, 0.f, 1.f);                         \
                float x0 = __shfl_xor_sync(0xffffffffu, v0, 1);                 \
                float x2 = __shfl_xor_sync(0xffffffffu, v2, 1);                 \
                float tc0 = 0.f, tc1 = 0.f;                                     \
                if (isE) {                                                      \
                    int ci = (mt * 4 + nt) * 2;                                 \
                    float cn0 = v1 * CS[ci] + v0 * x0;                          \
                    CS[ci] = cn0;                                               \
                    tc0 = actv(cn0, 2.f * L2E, 1.f, -2.f);                      \
                    float cn1 = v3 * CS[ci + 1] + v2 * x2;                      \
                    CS[ci + 1] = cn1;                                           \
                    tc1 = actv(cn1, 2.f * L2E, 1.f, -2.f);                      \
                }                                                               \
                float y0 = __shfl_xor_sync(0xffffffffu, tc0, 1);                \
                float y1 = __shfl_xor_sync(0xffffffffu, tc1, 1);                \
                if (!isE) {                                                     \
                    int hk = huO0 + 2 * nt;                                     \
                    int r0 = mt * 16 + lrow;                                    \
                    sts_h(HW, r0,     hk, __float2half_rn(v1 * y0));            \
                    sts_h(HW, r0 + 8, hk, __float2half_rn(v3 * y1));            \
                }                                                               \
            }                                                                   \
        }                                                                       \
    } while (0)

#pragma unroll 1
    for (int t = 0; t < TDIM; t++) {
        float d[2][4][4];
        const __half* zt = zbase + (size_t)t * (BDIM * GDIM);

        // ---- layer 0: D init from zx, then D += h0r @ Whh0 ----
#pragma unroll
        for (int mt = 0; mt < 2; mt++)
#pragma unroll
            for (int nt = 0; nt < 4; nt++) {
                __half2 za = *reinterpret_cast<const __half2*>(
                    zt + (size_t)(mt * 16) * GDIM + nt * 8);
                __half2 zb = *reinterpret_cast<const __half2*>(
                    zt + (size_t)(mt * 16 + 8) * GDIM + nt * 8);
                float2 fa = __half22float2(za);
                float2 fb = __half22float2(zb);
                d[mt][nt][0] = fa.x; d[mt][nt][1] = fa.y;
                d[mt][nt][2] = fb.x; d[mt][nt][3] = fb.y;
            }

        GEMM_ACC(h0buf[pp], Bw[0]);
        CELL(cs0, h0buf[pp ^ 1]);
        __syncthreads();

        // ---- layer 1: D init bias, D += h0_new @ Wih1 + h1_old @ Whh1 ----
#pragma unroll
        for (int mt = 0; mt < 2; mt++)
#pragma unroll
            for (int nt = 0; nt < 4; nt++) {
                d[mt][nt][0] = bias1[nt][0]; d[mt][nt][1] = bias1[nt][1];
                d[mt][nt][2] = bias1[nt][0]; d[mt][nt][3] = bias1[nt][1];
            }

        GEMM_ACC(h0buf[pp ^ 1], Bw[1]);
        GEMM_ACC(h1buf[pp],     Bw[2]);
        CELL(cs1, h1buf[pp ^ 1]);
        __syncthreads();

        pp ^= 1;
    }

    // ---- final FC on last h1 (now in h1buf[pp]) ----
    if (tid < MROWS) {
        const __half* hf = h1buf[pp];
        float s = bfc[0];
#pragma unroll 8
        for (int k = 0; k < HDIM; k++) {
            int off = tid * 128 + k * 2;
            off ^= (off >> 3) & 0x70;
            s += __half2float(*reinterpret_cast<const __half*>(
                     reinterpret_cast<const char*>(hf) + off)) * Wfc[k];
        }
        out[blockIdx.x * MROWS + tid] = s;
    }
}

// =====================================================================
extern "C" void kernel_launch(void* const* d_in, const int* in_sizes, int n_in,
                              void* d_out, int out_size)
{
    const float* x    = (const float*)d_in[0];
    const float* Wih0 = (const float*)d_in[1];
    const float* Whh0 = (const float*)d_in[2];
    const float* bih0 = (const float*)d_in[3];
    const float* bhh0 = (const float*)d_in[4];
    const float* Wih1 = (const float*)d_in[5];
    const float* Whh1 = (const float*)d_in[6];
    const float* bih1 = (const float*)d_in[7];
    const float* bhh1 = (const float*)d_in[8];
    const float* Wfc  = (const float*)d_in[9];
    const float* bfc  = (const float*)d_in[10];
    float* out = (float*)d_out;

    // 3 weight tiles (3*32KB) + 4 h buffers (4*4KB) = 112 KB
    const int smem_bytes = (3 * 256 * 64 + 4 * 2048) * 2;
    cudaFuncSetAttribute(lstm_kernel,
                         cudaFuncAttributeMaxDynamicSharedMemorySize, smem_bytes);

    dim3 pgrid(TDIM / TB, BDIM / BB);
    prep_kernel<<<pgrid, PNT>>>(x, Wih0, bih0, bhh0);
    lstm_kernel<<<LCTA, NT, smem_bytes>>>(Whh0, Wih1, Whh1, bih1, bhh1,
                                          Wfc, bfc, out);
}

// round 10
// speedup vs baseline: 1.7393x; 1.1116x over previous
#include <cuda_runtime.h>
#include <cuda_fp16.h>
#include <cstdint>
#include <cstddef>

// Problem constants
#define BDIM 4096
#define TDIM 168
#define IDIM 19
#define HDIM 64
#define GDIM 256          // 4*H
#define MROWS 32          // rows per CTA
#define LCTA 128          // lstm CTAs (128*32 = 4096)
#define NT   256

// 352 MB scratch: zx0[t][b][col] fp16, col = hu*4 + gate_type
__device__ __half g_zx[(size_t)TDIM * BDIM * GDIM];

// ---------------- f32x2 helpers (prep kernel) ----------------
__device__ __forceinline__ void fma2(unsigned long long& d,
                                     unsigned long long a,
                                     unsigned long long b) {
    asm("fma.rn.f32x2 %0, %1, %2, %0;" : "+l"(d) : "l"(a), "l"(b));
}
__device__ __forceinline__ unsigned long long pack2(float lo, float hi) {
    unsigned long long r;
    asm("mov.b64 %0, {%1, %2};" : "=l"(r) : "f"(lo), "f"(hi));
    return r;
}
__device__ __forceinline__ unsigned long long ld64(const float* p) {
    return *reinterpret_cast<const unsigned long long*>(p);
}

// ---------------- fast activations ----------------
__device__ __forceinline__ float ex2f(float x) {
    float y; asm("ex2.approx.f32 %0, %1;" : "=f"(y) : "f"(x)); return y;
}
__device__ __forceinline__ float rcpf(float x) {
    float y; asm("rcp.approx.f32 %0, %1;" : "=f"(y) : "f"(x)); return y;
}
#define L2E 1.4426950408889634f
// b + c / (1 + 2^(a*z)) :  sigmoid = (-L2E, 0, 1) ; tanh = (2*L2E, 1, -2)
__device__ __forceinline__ float actv(float z, float a, float b, float c) {
    return fmaf(c, rcpf(1.0f + ex2f(a * z)), b);
}

// ---------------- smem half-pair access with XOR swizzle ------
// rows are 64 halves = 128B; byte bits [6:4] ^= bits [9:7]
__device__ __forceinline__ uint32_t lds_hp(const __half* base, int row, int k) {
    int off = row * 128 + k * 2;
    off ^= (off >> 3) & 0x70;
    return *reinterpret_cast<const uint32_t*>(
        reinterpret_cast<const char*>(base) + off);
}
__device__ __forceinline__ void sts_h(__half* base, int row, int k, __half v) {
    int off = row * 128 + k * 2;
    off ^= (off >> 3) & 0x70;
    *reinterpret_cast<__half*>(reinterpret_cast<char*>(base) + off) = v;
}

// ---------------- mma / ldmatrix ----------------
__device__ __forceinline__ void mma16816(float* d, const uint32_t* a,
                                         const uint32_t* b) {
    asm volatile(
        "mma.sync.aligned.m16n8k16.row.col.f32.f16.f16.f32 "
        "{%0,%1,%2,%3},{%4,%5,%6,%7},{%8,%9},{%0,%1,%2,%3};"
        : "+f"(d[0]), "+f"(d[1]), "+f"(d[2]), "+f"(d[3])
        : "r"(a[0]), "r"(a[1]), "r"(a[2]), "r"(a[3]), "r"(b[0]), "r"(b[1]));
}
__device__ __forceinline__ void ldsm4(uint32_t* a, uint32_t addr) {
    asm volatile(
        "ldmatrix.sync.aligned.m8n8.x4.shared.b16 {%0,%1,%2,%3}, [%4];"
        : "=r"(a[0]), "=r"(a[1]), "=r"(a[2]), "=r"(a[3]) : "r"(addr));
}
__device__ __forceinline__ void ldsm2(uint32_t* b, uint32_t addr) {
    asm volatile(
        "ldmatrix.sync.aligned.m8n8.x2.shared.b16 {%0,%1}, [%2];"
        : "=r"(b[0]), "=r"(b[1]) : "r"(addr));
}
__device__ __forceinline__ uint32_t swz(uint32_t off) {
    return off ^ ((off >> 3) & 0x70);
}

// =====================================================================
// Prep kernel: g_zx[t][b][hu*4+gi] = x(b,t,:).Wih0 + bih0 + bhh0  (fp16 out)
// =====================================================================
#define TB 4
#define BB 32
#define PNT 256
__global__ void __launch_bounds__(PNT) prep_kernel(
    const float* __restrict__ x,
    const float* __restrict__ Wih0,
    const float* __restrict__ bih0,
    const float* __restrict__ bhh0)
{
    __shared__ __align__(16) float sW[IDIM * GDIM];
    __shared__ float sX[TB][BB][IDIM + 1];
    const int tid = threadIdx.x;
    const int t0 = blockIdx.x * TB;
    const int b0 = blockIdx.y * BB;

    for (int idx = tid; idx < IDIM * GDIM; idx += PNT) {
        int i  = idx >> 8;
        int c  = idx & 255;
        int hh = c >> 2, gi = c & 3;
        sW[idx] = Wih0[(gi * HDIM + hh) * IDIM + i];
    }
    for (int idx = tid; idx < TB * BB * IDIM; idx += PNT) {
        int i  = idx % IDIM;
        int rb = idx / IDIM;
        int bb = rb % BB, tt = rb / BB;
        sX[tt][bb][i] = x[((size_t)(b0 + bb) * TDIM + (t0 + tt)) * IDIM + i];
    }
    __syncthreads();

    const int hh = tid & 63;
    const int sub = tid >> 6;
    float bias[4];
#pragma unroll
    for (int gi = 0; gi < 4; gi++)
        bias[gi] = bih0[gi * HDIM + hh] + bhh0[gi * HDIM + hh];
    const unsigned long long b01 = pack2(bias[0], bias[1]);
    const unsigned long long b23 = pack2(bias[2], bias[3]);

    for (int tt = 0; tt < TB; tt++) {
#pragma unroll
        for (int j = 0; j < BB / 4; j++) {
            const int bb = sub * (BB / 4) + j;
            unsigned long long a01 = b01, a23 = b23;
#pragma unroll
            for (int i = 0; i < IDIM; i++) {
                float xv = sX[tt][bb][i];
                unsigned long long xp = pack2(xv, xv);
                const float* wp = &sW[i * GDIM + hh * 4];
                fma2(a01, xp, ld64(wp));
                fma2(a23, xp, ld64(wp + 2));
            }
            float r0, r1, r2, r3;
            asm("mov.b64 {%0, %1}, %2;" : "=f"(r0), "=f"(r1) : "l"(a01));
            asm("mov.b64 {%0, %1}, %2;" : "=f"(r2), "=f"(r3) : "l"(a23));
            __half2 h01 = __floats2half2_rn(r0, r1);
            __half2 h23 = __floats2half2_rn(r2, r3);
            uint2 o;
            o.x = *reinterpret_cast<uint32_t*>(&h01);
            o.y = *reinterpret_cast<uint32_t*>(&h23);
            *reinterpret_cast<uint2*>(
                &g_zx[(((size_t)(t0 + tt) * BDIM + (b0 + bb)) * HDIM + hh) * 4]) = o;
        }
    }
}

// =====================================================================
// LSTM kernel: 128 CTAs x 256 threads, 32 rows per CTA, fp16 HMMA.
// R9: reordered step (independent L1b GEMM first), ldmatrix for A frags,
//     L1a B-fragments streamed from smem (frees 32 regs).
// =====================================================================
__global__ void __launch_bounds__(NT, 1) lstm_kernel(
    const float* __restrict__ Whh0,
    const float* __restrict__ Wih1,
    const float* __restrict__ Whh1,
    const float* __restrict__ bih1,
    const float* __restrict__ bhh1,
    const float* __restrict__ Wfc,
    const float* __restrict__ bfc,
    float* __restrict__ out)
{
    extern __shared__ __align__(16) __half smem[];
    __half* sW0  = smem;                 // 256 x 64 halves (32 KB)
    __half* sW1a = sW0 + 256 * 64;       // Wih1 (32 KB)
    __half* sW1b = sW1a + 256 * 64;      // Whh1 (32 KB)
    __half* h0buf[2] = { sW1b + 256 * 64,        sW1b + 256 * 64 + 2048 };
    __half* h1buf[2] = { sW1b + 256 * 64 + 4096, sW1b + 256 * 64 + 6144 };

    const int tid  = threadIdx.x;
    const int w    = tid >> 5;           // warp 0..7
    const int lane = tid & 31;
    const int lrow = lane >> 2;          // 0..7
    const int lq   = lane & 3;           // 0..3
    const bool isE = (lane & 1) == 0;

    // ---- stage weights fp32 -> fp16, column order col = hu*4+ty ----
    for (int idx = tid; idx < 256 * 64; idx += NT) {
        int n = idx >> 6, k = idx & 63;
        int hu = n >> 2, ty = n & 3;
        int g = ty * HDIM + hu;
        sts_h(sW0,  n, k, __float2half_rn(Whh0[g * HDIM + k]));
        sts_h(sW1a, n, k, __float2half_rn(Wih1[g * HDIM + k]));
        sts_h(sW1b, n, k, __float2half_rn(Whh1[g * HDIM + k]));
    }
    for (int idx = tid; idx < 2048; idx += NT) {
        h0buf[0][idx] = __half(0.0f); h0buf[1][idx] = __half(0.0f);
        h1buf[0][idx] = __half(0.0f); h1buf[1][idx] = __half(0.0f);
    }
    __syncthreads();

    // ---- smem u32 bases for ldmatrix ----
    const uint32_t h0base[2] = {
        (uint32_t)__cvta_generic_to_shared(h0buf[0]),
        (uint32_t)__cvta_generic_to_shared(h0buf[1]) };
    const uint32_t h1base[2] = {
        (uint32_t)__cvta_generic_to_shared(h1buf[0]),
        (uint32_t)__cvta_generic_to_shared(h1buf[1]) };
    const uint32_t w1abase = (uint32_t)__cvta_generic_to_shared(sW1a);

    // per-lane A-frag offsets for ldmatrix.x4 (tile = lane>>3)
    //   tiles: 0:(m0-7,k0-7) 1:(m8-15,k0-7) 2:(m0-7,k8-15) 3:(m8-15,k8-15)
    const int a_rowpart = ((lane >> 3) & 1) * 8 + (lane & 7);
    const int a_colpart = (lane >> 4) * 16;        // bytes
    // per-lane B-frag offsets for ldmatrix.x2 (lanes 0-15; tile = k-half)
    const int bl   = lane & 15;
    const int b_rowbase = (w * 32 + (bl & 7)) * 128 + ((bl >> 3) * 16);

    // ---- preload B fragments for Whh0 (g=0) and Whh1 (g=2) ----
    uint32_t Bw0[4][4][2], Bw2[4][4][2];
#pragma unroll
    for (int nt = 0; nt < 4; nt++) {
        int n = w * 32 + nt * 8 + lrow;
#pragma unroll
        for (int kt = 0; kt < 4; kt++) {
            int k = kt * 16 + 2 * lq;
            Bw0[nt][kt][0] = lds_hp(sW0,  n, k);
            Bw0[nt][kt][1] = lds_hp(sW0,  n, k + 8);
            Bw2[nt][kt][0] = lds_hp(sW1b, n, k);
            Bw2[nt][kt][1] = lds_hp(sW1b, n, k + 8);
        }
    }

    // ---- L1 biases for my 8 columns ----
    float bias1[4][2];
#pragma unroll
    for (int nt = 0; nt < 4; nt++)
#pragma unroll
        for (int cc = 0; cc < 2; cc++) {
            int gcol = w * 32 + nt * 8 + 2 * lq + cc;
            int g = (gcol & 3) * HDIM + (gcol >> 2);
            bias1[nt][cc] = bih1[g] + bhh1[g];
        }

    // activation constants (E: sigmoid, O: tanh) for slots 0/2
    const float aA = isE ? -L2E : 2.0f * L2E;
    const float bA = isE ? 0.0f : 1.0f;
    const float cA = isE ? 1.0f : -2.0f;

    float cs0[16], cs1[16];
#pragma unroll
    for (int i = 0; i < 16; i++) { cs0[i] = 0.0f; cs1[i] = 0.0f; }

    const __half* zbase = g_zx +
        ((size_t)(blockIdx.x * MROWS + lrow) * GDIM + w * 32 + 2 * lq);
    const int huO0 = w * 8 + ((lq == 3) ? 1 : 0);

    int pp = 0;

    // A-frag ldmatrix over one (mt,kt) from buffer base HB (u32)
#define LDA(aa, HB, mt, kt)                                                     \
    do {                                                                        \
        uint32_t off = (uint32_t)(((mt) * 16 + a_rowpart) * 128 +               \
                                  (kt) * 32 + a_colpart);                       \
        ldsm4(aa, (HB) + swz(off));                                             \
    } while (0)

#define GEMM_LM(HB, BW, D)                                                      \
    do {                                                                        \
        _Pragma("unroll")                                                       \
        for (int mt = 0; mt < 2; mt++) {                                        \
            _Pragma("unroll")                                                   \
            for (int kt = 0; kt < 4; kt++) {                                    \
                uint32_t a[4];                                                  \
                LDA(a, HB, mt, kt);                                             \
                _Pragma("unroll")                                               \
                for (int nt = 0; nt < 4; nt++)                                  \
                    mma16816(D[mt][nt], a, BW[nt][kt]);                         \
            }                                                                   \
        }                                                                       \
    } while (0)

    // L1a GEMM: A from h0_new buffer, B streamed from sW1a via ldmatrix.x2
#define GEMM_L1A(HB, D)                                                         \
    do {                                                                        \
        _Pragma("unroll")                                                       \
        for (int kt = 0; kt < 4; kt++) {                                        \
            uint32_t a0[4], a1[4];                                              \
            LDA(a0, HB, 0, kt);                                                 \
            LDA(a1, HB, 1, kt);                                                 \
            _Pragma("unroll")                                                   \
            for (int nt = 0; nt < 4; nt++) {                                    \
                uint32_t b[2];                                                  \
                uint32_t boff = (uint32_t)(b_rowbase + nt * 1024 + kt * 32);    \
                ldsm2(b, w1abase + swz(boff));                                  \
                mma16816(D[0][nt], a0, b);                                      \
                mma16816(D[1][nt], a1, b);                                      \
            }                                                                   \
        }                                                                       \
    } while (0)

#define CELL(CS, HW)                                                            \
    do {                                                                        \
        _Pragma("unroll")                                                       \
        for (int mt = 0; mt < 2; mt++) {                                        \
            _Pragma("unroll")                                                   \
            for (int nt = 0; nt < 4; nt++) {                                    \
                float* dd = d[mt][nt];                                          \
                float v0 = actv(dd[0], aA, bA, cA);     /* E:si  O:tg  */       \
                float v1 = actv(dd[1], -L2E, 0.f, 1.f); /* E:sf  O:so  */       \
                float v2 = actv(dd[2], aA, bA, cA);                             \
                float v3 = actv(dd[3], -L2E, 0.f, 1.f);                         \
                float x0 = __shfl_xor_sync(0xffffffffu, v0, 1);                 \
                float x2 = __shfl_xor_sync(0xffffffffu, v2, 1);                 \
                float tc0 = 0.f, tc1 = 0.f;                                     \
                if (isE) {                                                      \
                    int ci = (mt * 4 + nt) * 2;                                 \
                    float cn0 = v1 * CS[ci] + v0 * x0;                          \
                    CS[ci] = cn0;                                               \
                    tc0 = actv(cn0, 2.f * L2E, 1.f, -2.f);                      \
                    float cn1 = v3 * CS[ci + 1] + v2 * x2;                      \
                    CS[ci + 1] = cn1;                                           \
                    tc1 = actv(cn1, 2.f * L2E, 1.f, -2.f);                      \
                }                                                               \
                float y0 = __shfl_xor_sync(0xffffffffu, tc0, 1);                \
                float y1 = __shfl_xor_sync(0xffffffffu, tc1, 1);                \
                if (!isE) {                                                     \
                    int hk = huO0 + 2 * nt;                                     \
                    int r0 = mt * 16 + lrow;                                    \
                    sts_h(HW, r0,     hk, __float2half_rn(v1 * y0));            \
                    sts_h(HW, r0 + 8, hk, __float2half_rn(v3 * y1));            \
                }                                                               \
            }                                                                   \
        }                                                                       \
    } while (0)

#pragma unroll 1
    for (int t = 0; t < TDIM; t++) {
        float d0[2][4][4], d1[2][4][4];
        const __half* zt = zbase + (size_t)t * (BDIM * GDIM);

        // ---- issue zx loads first (latency covered by L1b GEMM) ----
        uint32_t zr[16];
#pragma unroll
        for (int mt = 0; mt < 2; mt++)
#pragma unroll
            for (int nt = 0; nt < 4; nt++) {
                zr[(mt * 4 + nt) * 2 + 0] = *reinterpret_cast<const uint32_t*>(
                    zt + (size_t)(mt * 16) * GDIM + nt * 8);
                zr[(mt * 4 + nt) * 2 + 1] = *reinterpret_cast<const uint32_t*>(
                    zt + (size_t)(mt * 16 + 8) * GDIM + nt * 8);
            }

        // ---- d1 = bias ; d1 += h1_old @ Whh1  (independent of layer 0) ----
#pragma unroll
        for (int mt = 0; mt < 2; mt++)
#pragma unroll
            for (int nt = 0; nt < 4; nt++) {
                d1[mt][nt][0] = bias1[nt][0]; d1[mt][nt][1] = bias1[nt][1];
                d1[mt][nt][2] = bias1[nt][0]; d1[mt][nt][3] = bias1[nt][1];
            }
        GEMM_LM(h1base[pp], Bw2, d1);

        // ---- d0 = zx ; d0 += h0_old @ Whh0 ----
#pragma unroll
        for (int mt = 0; mt < 2; mt++)
#pragma unroll
            for (int nt = 0; nt < 4; nt++) {
                __half2 za = *reinterpret_cast<const __half2*>(
                    &zr[(mt * 4 + nt) * 2 + 0]);
                __half2 zb = *reinterpret_cast<const __half2*>(
                    &zr[(mt * 4 + nt) * 2 + 1]);
                float2 fa = __half22float2(za);
                float2 fb = __half22float2(zb);
                d0[mt][nt][0] = fa.x; d0[mt][nt][1] = fa.y;
                d0[mt][nt][2] = fb.x; d0[mt][nt][3] = fb.y;
            }
        GEMM_LM(h0base[pp], Bw0, d0);

        // ---- cell 0 -> h0_new ----
        {
            float (*d)[4][4] = d0;
            CELL(cs0, h0buf[pp ^ 1]);
        }
        __syncthreads();

        // ---- d1 += h0_new @ Wih1 ; cell 1 -> h1_new ----
        GEMM_L1A(h0base[pp ^ 1], d1);
        {
            float (*d)[4][4] = d1;
            CELL(cs1, h1buf[pp ^ 1]);
        }
        __syncthreads();

        pp ^= 1;
    }

    // ---- final FC on last h1 (now in h1buf[pp]) ----
    if (tid < MROWS) {
        const __half* hf = h1buf[pp];
        float s = bfc[0];
#pragma unroll 8
        for (int k = 0; k < HDIM; k++) {
            int off = tid * 128 + k * 2;
            off ^= (off >> 3) & 0x70;
            s += __half2float(*reinterpret_cast<const __half*>(
                     reinterpret_cast<const char*>(hf) + off)) * Wfc[k];
        }
        out[blockIdx.x * MROWS + tid] = s;
    }
}

// =====================================================================
extern "C" void kernel_launch(void* const* d_in, const int* in_sizes, int n_in,
                              void* d_out, int out_size)
{
    const float* x    = (const float*)d_in[0];
    const float* Wih0 = (const float*)d_in[1];
    const float* Whh0 = (const float*)d_in[2];
    const float* bih0 = (const float*)d_in[3];
    const float* bhh0 = (const float*)d_in[4];
    const float* Wih1 = (const float*)d_in[5];
    const float* Whh1 = (const float*)d_in[6];
    const float* bih1 = (const float*)d_in[7];
    const float* bhh1 = (const float*)d_in[8];
    const float* Wfc  = (const float*)d_in[9];
    const float* bfc  = (const float*)d_in[10];
    float* out = (float*)d_out;

    const int smem_bytes = (3 * 256 * 64 + 4 * 2048) * 2;
    cudaFuncSetAttribute(lstm_kernel,
                         cudaFuncAttributeMaxDynamicSharedMemorySize, smem_bytes);

    dim3 pgrid(TDIM / TB, BDIM / BB);
    prep_kernel<<<pgrid, PNT>>>(x, Wih0, bih0, bhh0);
    lstm_kernel<<<LCTA, NT, smem_bytes>>>(Whh0, Wih1, Whh1, bih1, bhh1,
                                          Wfc, bfc, out);
}

// round 12
// speedup vs baseline: 2.0960x; 1.2051x over previous
#include <cuda_runtime.h>
#include <cuda_fp16.h>
#include <cstdint>
#include <cstddef>

// Problem constants
#define BDIM 4096
#define TDIM 168
#define IDIM 19
#define HDIM 64
#define GDIM 256          // 4*H
#define MROWS 32          // rows per CTA
#define LCTA 128          // lstm CTAs (128*32 = 4096)
#define NT   512          // 16 warps: wq = w&7 (32 cols), wm = w>>3 (16 rows)

// 352 MB scratch: zx0[t][b][col] fp16, col = hu*4 + gate_type
__device__ __half g_zx[(size_t)TDIM * BDIM * GDIM];

// ---------------- f32x2 helpers (prep kernel) ----------------
__device__ __forceinline__ void fma2(unsigned long long& d,
                                     unsigned long long a,
                                     unsigned long long b) {
    asm("fma.rn.f32x2 %0, %1, %2, %0;" : "+l"(d) : "l"(a), "l"(b));
}
__device__ __forceinline__ unsigned long long pack2(float lo, float hi) {
    unsigned long long r;
    asm("mov.b64 %0, {%1, %2};" : "=l"(r) : "f"(lo), "f"(hi));
    return r;
}
__device__ __forceinline__ unsigned long long ld64(const float* p) {
    return *reinterpret_cast<const unsigned long long*>(p);
}

// ---------------- fast activations ----------------
__device__ __forceinline__ float ex2f(float x) {
    float y; asm("ex2.approx.f32 %0, %1;" : "=f"(y) : "f"(x)); return y;
}
__device__ __forceinline__ float rcpf(float x) {
    float y; asm("rcp.approx.f32 %0, %1;" : "=f"(y) : "f"(x)); return y;
}
#define L2E 1.4426950408889634f
// b + c / (1 + 2^(a*z)) :  sigmoid = (-L2E, 0, 1) ; tanh = (2*L2E, 1, -2)
__device__ __forceinline__ float actv(float z, float a, float b, float c) {
    return fmaf(c, rcpf(1.0f + ex2f(a * z)), b);
}

// ---------------- smem half access with XOR swizzle ------
__device__ __forceinline__ void sts_h(__half* base, int row, int k, __half v) {
    int off = row * 128 + k * 2;
    off ^= (off >> 3) & 0x70;
    *reinterpret_cast<__half*>(reinterpret_cast<char*>(base) + off) = v;
}
__device__ __forceinline__ uint32_t swz(uint32_t off) {
    return off ^ ((off >> 3) & 0x70);
}

// ---------------- mma / ldmatrix ----------------
__device__ __forceinline__ void mma16816(float* d, const uint32_t* a,
                                         const uint32_t* b) {
    asm volatile(
        "mma.sync.aligned.m16n8k16.row.col.f32.f16.f16.f32 "
        "{%0,%1,%2,%3},{%4,%5,%6,%7},{%8,%9},{%0,%1,%2,%3};"
        : "+f"(d[0]), "+f"(d[1]), "+f"(d[2]), "+f"(d[3])
        : "r"(a[0]), "r"(a[1]), "r"(a[2]), "r"(a[3]), "r"(b[0]), "r"(b[1]));
}
__device__ __forceinline__ void ldsm4(uint32_t* a, uint32_t addr) {
    asm volatile(
        "ldmatrix.sync.aligned.m8n8.x4.shared.b16 {%0,%1,%2,%3}, [%4];"
        : "=r"(a[0]), "=r"(a[1]), "=r"(a[2]), "=r"(a[3]) : "r"(addr));
}
__device__ __forceinline__ void ldsm2(uint32_t* b, uint32_t addr) {
    asm volatile(
        "ldmatrix.sync.aligned.m8n8.x2.shared.b16 {%0,%1}, [%2];"
        : "=r"(b[0]), "=r"(b[1]) : "r"(addr));
}

// ---------------- named barrier ----------------
__device__ __forceinline__ void barn(int id, int cnt) {
    asm volatile("bar.sync %0, %1;" :: "r"(id), "r"(cnt) : "memory");
}

// =====================================================================
// Prep kernel: g_zx[t][b][hu*4+gi] = x(b,t,:).Wih0 + bih0 + bhh0  (fp16 out)
// =====================================================================
#define TB 4
#define BB 32
#define PNT 256
__global__ void __launch_bounds__(PNT) prep_kernel(
    const float* __restrict__ x,
    const float* __restrict__ Wih0,
    const float* __restrict__ bih0,
    const float* __restrict__ bhh0)
{
    __shared__ __align__(16) float sW[IDIM * GDIM];
    __shared__ float sX[TB][BB][IDIM + 1];
    const int tid = threadIdx.x;
    const int t0 = blockIdx.x * TB;
    const int b0 = blockIdx.y * BB;

    for (int idx = tid; idx < IDIM * GDIM; idx += PNT) {
        int i  = idx >> 8;
        int c  = idx & 255;
        int hh = c >> 2, gi = c & 3;
        sW[idx] = Wih0[(gi * HDIM + hh) * IDIM + i];
    }
    for (int idx = tid; idx < TB * BB * IDIM; idx += PNT) {
        int i  = idx % IDIM;
        int rb = idx / IDIM;
        int bb = rb % BB, tt = rb / BB;
        sX[tt][bb][i] = x[((size_t)(b0 + bb) * TDIM + (t0 + tt)) * IDIM + i];
    }
    __syncthreads();

    const int hh = tid & 63;
    const int sub = tid >> 6;
    float bias[4];
#pragma unroll
    for (int gi = 0; gi < 4; gi++)
        bias[gi] = bih0[gi * HDIM + hh] + bhh0[gi * HDIM + hh];
    const unsigned long long b01 = pack2(bias[0], bias[1]);
    const unsigned long long b23 = pack2(bias[2], bias[3]);

    for (int tt = 0; tt < TB; tt++) {
#pragma unroll
        for (int j = 0; j < BB / 4; j++) {
            const int bb = sub * (BB / 4) + j;
            unsigned long long a01 = b01, a23 = b23;
#pragma unroll
            for (int i = 0; i < IDIM; i++) {
                float xv = sX[tt][bb][i];
                unsigned long long xp = pack2(xv, xv);
                const float* wp = &sW[i * GDIM + hh * 4];
                fma2(a01, xp, ld64(wp));
                fma2(a23, xp, ld64(wp + 2));
            }
            float r0, r1, r2, r3;
            asm("mov.b64 {%0, %1}, %2;" : "=f"(r0), "=f"(r1) : "l"(a01));
            asm("mov.b64 {%0, %1}, %2;" : "=f"(r2), "=f"(r3) : "l"(a23));
            __half2 h01 = __floats2half2_rn(r0, r1);
            __half2 h23 = __floats2half2_rn(r2, r3);
            uint2 o;
            o.x = *reinterpret_cast<uint32_t*>(&h01);
            o.y = *reinterpret_cast<uint32_t*>(&h23);
            *reinterpret_cast<uint2*>(
                &g_zx[(((size_t)(t0 + tt) * BDIM + (b0 + bb)) * HDIM + hh) * 4]) = o;
        }
    }
}

// =====================================================================
// LSTM kernel: 128 CTAs x 512 threads (16 warps), fp16 HMMA.
// Warp (wq, wm): cols [32wq,32wq+32), rows [16wm,16wm+16).
// All B-fragments streamed from smem via ldmatrix.x2 (regs ~100 -> no cap).
// Row-halves fully decoupled -> per-wm named barriers (de-phased halves).
// =====================================================================
__global__ void __launch_bounds__(NT, 1) lstm_kernel(
    const float* __restrict__ Whh0,
    const float* __restrict__ Wih1,
    const float* __restrict__ Whh1,
    const float* __restrict__ bih1,
    const float* __restrict__ bhh1,
    const float* __restrict__ Wfc,
    const float* __restrict__ bfc,
    float* __restrict__ out)
{
    extern __shared__ __align__(16) __half smem[];
    __half* sW0  = smem;                 // Whh0: 256 x 64 halves (32 KB)
    __half* sW1a = sW0 + 256 * 64;       // Wih1 (32 KB)
    __half* sW1b = sW1a + 256 * 64;      // Whh1 (32 KB)
    __half* h0buf[2] = { sW1b + 256 * 64,        sW1b + 256 * 64 + 2048 };
    __half* h1buf[2] = { sW1b + 256 * 64 + 4096, sW1b + 256 * 64 + 6144 };

    const int tid  = threadIdx.x;
    const int w    = tid >> 5;
    const int wq   = w & 7;              // column group
    const int wm   = w >> 3;             // row half
    const int lane = tid & 31;
    const int lrow = lane >> 2;          // 0..7
    const int lq   = lane & 3;           // 0..3
    const bool isE = (lane & 1) == 0;

    // ---- stage weights fp32 -> fp16, column order col = hu*4+ty ----
    for (int idx = tid; idx < 256 * 64; idx += NT) {
        int n = idx >> 6, k = idx & 63;
        int hu = n >> 2, ty = n & 3;
        int g = ty * HDIM + hu;
        sts_h(sW0,  n, k, __float2half_rn(Whh0[g * HDIM + k]));
        sts_h(sW1a, n, k, __float2half_rn(Wih1[g * HDIM + k]));
        sts_h(sW1b, n, k, __float2half_rn(Whh1[g * HDIM + k]));
    }
    for (int idx = tid; idx < 2048; idx += NT) {
        h0buf[0][idx] = __half(0.0f); h0buf[1][idx] = __half(0.0f);
        h1buf[0][idx] = __half(0.0f); h1buf[1][idx] = __half(0.0f);
    }
    __syncthreads();

    const uint32_t h0base[2] = {
        (uint32_t)__cvta_generic_to_shared(h0buf[0]),
        (uint32_t)__cvta_generic_to_shared(h0buf[1]) };
    const uint32_t h1base[2] = {
        (uint32_t)__cvta_generic_to_shared(h1buf[0]),
        (uint32_t)__cvta_generic_to_shared(h1buf[1]) };
    const uint32_t w0base  = (uint32_t)__cvta_generic_to_shared(sW0);
    const uint32_t w1abase = (uint32_t)__cvta_generic_to_shared(sW1a);
    const uint32_t w1bbase = (uint32_t)__cvta_generic_to_shared(sW1b);

    // A-frag lane offsets (ldmatrix.x4 over 16 rows x 16 cols)
    const int a_rowpart = ((lane >> 3) & 1) * 8 + (lane & 7);
    const int a_colpart = (lane >> 4) * 16;        // bytes
    // B-frag lane offsets (ldmatrix.x2, lanes 0-15)
    const int bl = lane & 15;
    const int b_rowbase = (wq * 32 + (bl & 7)) * 128 + ((bl >> 3) * 16);

    // ---- L1 biases for my 8 columns ----
    float bias1[4][2];
#pragma unroll
    for (int nt = 0; nt < 4; nt++)
#pragma unroll
        for (int cc = 0; cc < 2; cc++) {
            int gcol = wq * 32 + nt * 8 + 2 * lq + cc;
            int g = (gcol & 3) * HDIM + (gcol >> 2);
            bias1[nt][cc] = bih1[g] + bhh1[g];
        }

    // activation constants (E: sigmoid, O: tanh) for slots 0/2
    const float aA = isE ? -L2E : 2.0f * L2E;
    const float bA = isE ? 0.0f : 1.0f;
    const float cA = isE ? 1.0f : -2.0f;

    float cs0[8], cs1[8];
#pragma unroll
    for (int i = 0; i < 8; i++) { cs0[i] = 0.0f; cs1[i] = 0.0f; }

    const __half* zbase = g_zx +
        ((size_t)(blockIdx.x * MROWS + wm * 16 + lrow) * GDIM + wq * 32 + 2 * lq);
    const int huO0 = wq * 8 + ((lq == 3) ? 1 : 0);
    const int bid = 1 + wm;              // per-row-half barrier (256 threads)

    int pp = 0;

#define LDA(aa, HB, kt)                                                         \
    do {                                                                        \
        uint32_t off = (uint32_t)((wm * 16 + a_rowpart) * 128 +                 \
                                  (kt) * 32 + a_colpart);                       \
        ldsm4(aa, (HB) + swz(off));                                             \
    } while (0)

    // GEMM: A from h buffer (own 16 rows), B streamed from weight tile WB
#define GEMM_S(HB, WB, D)                                                       \
    do {                                                                        \
        _Pragma("unroll")                                                       \
        for (int kt = 0; kt < 4; kt++) {                                        \
            uint32_t a[4];                                                      \
            LDA(a, HB, kt);                                                     \
            _Pragma("unroll")                                                   \
            for (int nt = 0; nt < 4; nt++) {                                    \
                uint32_t b[2];                                                  \
                uint32_t boff = (uint32_t)(b_rowbase + nt * 1024 + kt * 32);    \
                ldsm2(b, (WB) + swz(boff));                                     \
                mma16816(D[nt], a, b);                                          \
            }                                                                   \
        }                                                                       \
    } while (0)

#define CELL(CS, HW, D)                                                         \
    do {                                                                        \
        _Pragma("unroll")                                                       \
        for (int nt = 0; nt < 4; nt++) {                                        \
            float* dd = D[nt];                                                  \
            float v0 = actv(dd[0], aA, bA, cA);     /* E:si  O:tg  */           \
            float v1 = actv(dd[1], -L2E, 0.f, 1.f); /* E:sf  O:so  */           \
            float v2 = actv(dd[2], aA, bA, cA);                                 \
            float v3 = actv(dd[3], -L2E, 0.f, 1.f);                             \
            float x0 = __shfl_xor_sync(0xffffffffu, v0, 1);                     \
            float x2 = __shfl_xor_sync(0xffffffffu, v2, 1);                     \
            float tc0 = 0.f, tc1 = 0.f;                                         \
            if (isE) {                                                          \
                float cn0 = v1 * CS[nt * 2] + v0 * x0;                          \
                CS[nt * 2] = cn0;                                               \
                tc0 = actv(cn0, 2.f * L2E, 1.f, -2.f);                          \
                float cn1 = v3 * CS[nt * 2 + 1] + v2 * x2;                      \
                CS[nt * 2 + 1] = cn1;                                           \
                tc1 = actv(cn1, 2.f * L2E, 1.f, -2.f);                          \
            }                                                                   \
            float y0 = __shfl_xor_sync(0xffffffffu, tc0, 1);                    \
            float y1 = __shfl_xor_sync(0xffffffffu, tc1, 1);                    \
            if (!isE) {                                                         \
                int hk = huO0 + 2 * nt;                                         \
                int r0 = wm * 16 + lrow;                                        \
                sts_h(HW, r0,     hk, __float2half_rn(v1 * y0));                \
                sts_h(HW, r0 + 8, hk, __float2half_rn(v3 * y1));                \
            }                                                                   \
        }                                                                       \
    } while (0)

#pragma unroll 1
    for (int t = 0; t < TDIM; t++) {
        float d0[4][4], d1[4][4];
        const __half* zt = zbase + (size_t)t * (BDIM * GDIM);

        // zx loads first (latency hidden by L1b GEMM)
        uint32_t zr[8];
#pragma unroll
        for (int nt = 0; nt < 4; nt++) {
            zr[nt * 2 + 0] = *reinterpret_cast<const uint32_t*>(zt + nt * 8);
            zr[nt * 2 + 1] = *reinterpret_cast<const uint32_t*>(
                zt + (size_t)8 * GDIM + nt * 8);
        }

        // d1 = bias ; d1 += h1_old @ Whh1  (independent of layer 0)
#pragma unroll
        for (int nt = 0; nt < 4; nt++) {
            d1[nt][0] = bias1[nt][0]; d1[nt][1] = bias1[nt][1];
            d1[nt][2] = bias1[nt][0]; d1[nt][3] = bias1[nt][1];
        }
        GEMM_S(h1base[pp], w1bbase, d1);

        // d0 = zx ; d0 += h0_old @ Whh0
#pragma unroll
        for (int nt = 0; nt < 4; nt++) {
            __half2 za = *reinterpret_cast<const __half2*>(&zr[nt * 2 + 0]);
            __half2 zb = *reinterpret_cast<const __half2*>(&zr[nt * 2 + 1]);
            float2 fa = __half22float2(za);
            float2 fb = __half22float2(zb);
            d0[nt][0] = fa.x; d0[nt][1] = fa.y;
            d0[nt][2] = fb.x; d0[nt][3] = fb.y;
        }
        GEMM_S(h0base[pp], w0base, d0);

        // cell 0 -> h0_new
        CELL(cs0, h0buf[pp ^ 1], d0);
        barn(bid, 256);                 // own row-half only

        // d1 += h0_new @ Wih1 ; cell 1 -> h1_new
        GEMM_S(h0base[pp ^ 1], w1abase, d1);
        CELL(cs1, h1buf[pp ^ 1], d1);
        barn(bid, 256);

        pp ^= 1;
    }

    __syncthreads();

    // ---- final FC on last h1 (now in h1buf[pp]) ----
    if (tid < MROWS) {
        const __half* hf = h1buf[pp];
        float s = bfc[0];
#pragma unroll 8
        for (int k = 0; k < HDIM; k++) {
            int off = tid * 128 + k * 2;
            off ^= (off >> 3) & 0x70;
            s += __half2float(*reinterpret_cast<const __half*>(
                     reinterpret_cast<const char*>(hf) + off)) * Wfc[k];
        }
        out[blockIdx.x * MROWS + tid] = s;
    }
}

// =====================================================================
extern "C" void kernel_launch(void* const* d_in, const int* in_sizes, int n_in,
                              void* d_out, int out_size)
{
    const float* x    = (const float*)d_in[0];
    const float* Wih0 = (const float*)d_in[1];
    const float* Whh0 = (const float*)d_in[2];
    const float* bih0 = (const float*)d_in[3];
    const float* bhh0 = (const float*)d_in[4];
    const float* Wih1 = (const float*)d_in[5];
    const float* Whh1 = (const float*)d_in[6];
    const float* bih1 = (const float*)d_in[7];
    const float* bhh1 = (const float*)d_in[8];
    const float* Wfc  = (const float*)d_in[9];
    const float* bfc  = (const float*)d_in[10];
    float* out = (float*)d_out;

    const int smem_bytes = (3 * 256 * 64 + 4 * 2048) * 2;
    cudaFuncSetAttribute(lstm_kernel,
                         cudaFuncAttributeMaxDynamicSharedMemorySize, smem_bytes);

    dim3 pgrid(TDIM / TB, BDIM / BB);
    prep_kernel<<<pgrid, PNT>>>(x, Wih0, bih0, bhh0);
    lstm_kernel<<<LCTA, NT, smem_bytes>>>(Whh0, Wih1, Whh1, bih1, bhh1,
                                          Wfc, bfc, out);
}

// round 14
// speedup vs baseline: 2.6317x; 1.2556x over previous
#include <cuda_runtime.h>
#include <cuda_fp16.h>
#include <cstdint>
#include <cstddef>

// Problem constants
#define BDIM 4096
#define TDIM 168
#define IDIM 19
#define HDIM 64
#define GDIM 256          // 4*H
#define MROWS 32          // rows per CTA
#define LCTA 128          // lstm CTAs (128*32 = 4096)
#define NT   512          // 16 warps: wq = w&7 (32 cols), wm = w>>3 (16 rows)

// 352 MB scratch: zx0[t][b][col] fp16, col = hu*4 + gate_type (i,f,g,o)
__device__ __half g_zx[(size_t)TDIM * BDIM * GDIM];

// ---------------- f32x2 helpers (prep kernel) ----------------
__device__ __forceinline__ void fma2(unsigned long long& d,
                                     unsigned long long a,
                                     unsigned long long b) {
    asm("fma.rn.f32x2 %0, %1, %2, %0;" : "+l"(d) : "l"(a), "l"(b));
}
__device__ __forceinline__ unsigned long long pack2(float lo, float hi) {
    unsigned long long r;
    asm("mov.b64 %0, {%1, %2};" : "=l"(r) : "f"(lo), "f"(hi));
    return r;
}
__device__ __forceinline__ unsigned long long ld64(const float* p) {
    return *reinterpret_cast<const unsigned long long*>(p);
}

// ---------------- fast activations ----------------
__device__ __forceinline__ float ex2f(float x) {
    float y; asm("ex2.approx.f32 %0, %1;" : "=f"(y) : "f"(x)); return y;
}
__device__ __forceinline__ float rcpf(float x) {
    float y; asm("rcp.approx.f32 %0, %1;" : "=f"(y) : "f"(x)); return y;
}
#define L2E 1.4426950408889634f
__device__ __forceinline__ float sigm(float z) {
    return rcpf(1.0f + ex2f(-L2E * z));
}
__device__ __forceinline__ float tanh_(float z) {
    return fmaf(-2.0f, rcpf(1.0f + ex2f(2.0f * L2E * z)), 1.0f);
}

// ---------------- smem half access with XOR swizzle ------
__device__ __forceinline__ void sts_h(__half* base, int row, int k, __half v) {
    int off = row * 128 + k * 2;
    off ^= (off >> 3) & 0x70;
    *reinterpret_cast<__half*>(reinterpret_cast<char*>(base) + off) = v;
}
__device__ __forceinline__ uint32_t swz(uint32_t off) {
    return off ^ ((off >> 3) & 0x70);
}

// ---------------- mma / ldmatrix ----------------
__device__ __forceinline__ void mma16816(float* d, const uint32_t* a,
                                         const uint32_t* b) {
    asm volatile(
        "mma.sync.aligned.m16n8k16.row.col.f32.f16.f16.f32 "
        "{%0,%1,%2,%3},{%4,%5,%6,%7},{%8,%9},{%0,%1,%2,%3};"
        : "+f"(d[0]), "+f"(d[1]), "+f"(d[2]), "+f"(d[3])
        : "r"(a[0]), "r"(a[1]), "r"(a[2]), "r"(a[3]), "r"(b[0]), "r"(b[1]));
}
__device__ __forceinline__ void ldsm4(uint32_t* a, uint32_t addr) {
    asm volatile(
        "ldmatrix.sync.aligned.m8n8.x4.shared.b16 {%0,%1,%2,%3}, [%4];"
        : "=r"(a[0]), "=r"(a[1]), "=r"(a[2]), "=r"(a[3]) : "r"(addr));
}
__device__ __forceinline__ void ldsm2(uint32_t* b, uint32_t addr) {
    asm volatile(
        "ldmatrix.sync.aligned.m8n8.x2.shared.b16 {%0,%1}, [%2];"
        : "=r"(b[0]), "=r"(b[1]) : "r"(addr));
}

// ---------------- named barrier ----------------
__device__ __forceinline__ void barn(int id, int cnt) {
    asm volatile("bar.sync %0, %1;" :: "r"(id), "r"(cnt) : "memory");
}

// smem weight-column permutation: column n -> torch gate row g.
// n = wq*32 + nt*8 + 2*lq + c  maps to  hu = wq*8 + (nt>>1)*4 + lq,
// gi = (nt&1)*2 + c  ->  g = gi*64 + hu.
// Result: thread lq's two col-pairs in n-tiles (0,1) / (2,3) hold all 4
// gates (i,f | g,o) of hu_A / hu_B -> thread-local cell update, no shfl.
__device__ __forceinline__ int colmap(int n) {
    int wq_ = n >> 5, r = n & 31;
    int nt = r >> 3, lq_ = (r & 7) >> 1, c = r & 1;
    int hu = wq_ * 8 + (nt >> 1) * 4 + lq_;
    int gi = (nt & 1) * 2 + c;
    return gi * HDIM + hu;
}

// =====================================================================
// Prep kernel: g_zx[t][b][hu*4+gi] = x(b,t,:).Wih0 + bih0 + bhh0  (fp16 out)
// =====================================================================
#define TB 4
#define BB 32
#define PNT 256
__global__ void __launch_bounds__(PNT) prep_kernel(
    const float* __restrict__ x,
    const float* __restrict__ Wih0,
    const float* __restrict__ bih0,
    const float* __restrict__ bhh0)
{
    __shared__ __align__(16) float sW[IDIM * GDIM];
    __shared__ float sX[TB][BB][IDIM + 1];
    const int tid = threadIdx.x;
    const int t0 = blockIdx.x * TB;
    const int b0 = blockIdx.y * BB;

    for (int idx = tid; idx < IDIM * GDIM; idx += PNT) {
        int i  = idx >> 8;
        int c  = idx & 255;
        int hh = c >> 2, gi = c & 3;
        sW[idx] = Wih0[(gi * HDIM + hh) * IDIM + i];
    }
    for (int idx = tid; idx < TB * BB * IDIM; idx += PNT) {
        int i  = idx % IDIM;
        int rb = idx / IDIM;
        int bb = rb % BB, tt = rb / BB;
        sX[tt][bb][i] = x[((size_t)(b0 + bb) * TDIM + (t0 + tt)) * IDIM + i];
    }
    __syncthreads();

    const int hh = tid & 63;
    const int sub = tid >> 6;
    float bias[4];
#pragma unroll
    for (int gi = 0; gi < 4; gi++)
        bias[gi] = bih0[gi * HDIM + hh] + bhh0[gi * HDIM + hh];
    const unsigned long long b01 = pack2(bias[0], bias[1]);
    const unsigned long long b23 = pack2(bias[2], bias[3]);

    for (int tt = 0; tt < TB; tt++) {
#pragma unroll
        for (int j = 0; j < BB / 4; j++) {
            const int bb = sub * (BB / 4) + j;
            unsigned long long a01 = b01, a23 = b23;
#pragma unroll
            for (int i = 0; i < IDIM; i++) {
                float xv = sX[tt][bb][i];
                unsigned long long xp = pack2(xv, xv);
                const float* wp = &sW[i * GDIM + hh * 4];
                fma2(a01, xp, ld64(wp));
                fma2(a23, xp, ld64(wp + 2));
            }
            float r0, r1, r2, r3;
            asm("mov.b64 {%0, %1}, %2;" : "=f"(r0), "=f"(r1) : "l"(a01));
            asm("mov.b64 {%0, %1}, %2;" : "=f"(r2), "=f"(r3) : "l"(a23));
            __half2 h01 = __floats2half2_rn(r0, r1);
            __half2 h23 = __floats2half2_rn(r2, r3);
            uint2 o;
            o.x = *reinterpret_cast<uint32_t*>(&h01);
            o.y = *reinterpret_cast<uint32_t*>(&h23);
            *reinterpret_cast<uint2*>(
                &g_zx[(((size_t)(t0 + tt) * BDIM + (b0 + bb)) * HDIM + hh) * 4]) = o;
        }
    }
}

// =====================================================================
// LSTM kernel: 128 CTAs x 512 threads (16 warps), fp16 HMMA.
// Warp (wq, wm): cols [32wq,32wq+32), rows [16wm,16wm+16).
// NEW column permutation -> fully thread-local CELL (no shfl, no E/O split).
// =====================================================================
__global__ void __launch_bounds__(NT, 1) lstm_kernel(
    const float* __restrict__ Whh0,
    const float* __restrict__ Wih1,
    const float* __restrict__ Whh1,
    const float* __restrict__ bih1,
    const float* __restrict__ bhh1,
    const float* __restrict__ Wfc,
    const float* __restrict__ bfc,
    float* __restrict__ out)
{
    extern __shared__ __align__(16) __half smem[];
    __half* sW0  = smem;                 // Whh0: 256 x 64 halves (32 KB)
    __half* sW1a = sW0 + 256 * 64;       // Wih1 (32 KB)
    __half* sW1b = sW1a + 256 * 64;      // Whh1 (32 KB)
    __half* h0buf[2] = { sW1b + 256 * 64,        sW1b + 256 * 64 + 2048 };
    __half* h1buf[2] = { sW1b + 256 * 64 + 4096, sW1b + 256 * 64 + 6144 };

    const int tid  = threadIdx.x;
    const int w    = tid >> 5;
    const int wq   = w & 7;              // column group
    const int wm   = w >> 3;             // row half
    const int lane = tid & 31;
    const int lrow = lane >> 2;          // 0..7
    const int lq   = lane & 3;           // 0..3

    // ---- stage weights fp32 -> fp16 with the thread-local permutation ----
    for (int idx = tid; idx < 256 * 64; idx += NT) {
        int n = idx >> 6, k = idx & 63;
        int g = colmap(n);
        sts_h(sW0,  n, k, __float2half_rn(Whh0[g * HDIM + k]));
        sts_h(sW1a, n, k, __float2half_rn(Wih1[g * HDIM + k]));
        sts_h(sW1b, n, k, __float2half_rn(Whh1[g * HDIM + k]));
    }
    for (int idx = tid; idx < 2048; idx += NT) {
        h0buf[0][idx] = __half(0.0f); h0buf[1][idx] = __half(0.0f);
        h1buf[0][idx] = __half(0.0f); h1buf[1][idx] = __half(0.0f);
    }
    __syncthreads();

    const uint32_t h0base[2] = {
        (uint32_t)__cvta_generic_to_shared(h0buf[0]),
        (uint32_t)__cvta_generic_to_shared(h0buf[1]) };
    const uint32_t h1base[2] = {
        (uint32_t)__cvta_generic_to_shared(h1buf[0]),
        (uint32_t)__cvta_generic_to_shared(h1buf[1]) };
    const uint32_t w0base  = (uint32_t)__cvta_generic_to_shared(sW0);
    const uint32_t w1abase = (uint32_t)__cvta_generic_to_shared(sW1a);
    const uint32_t w1bbase = (uint32_t)__cvta_generic_to_shared(sW1b);

    // A-frag lane offsets (ldmatrix.x4 over 16 rows x 16 cols)
    const int a_rowpart = ((lane >> 3) & 1) * 8 + (lane & 7);
    const int a_colpart = (lane >> 4) * 16;        // bytes
    // B-frag lane offsets (ldmatrix.x2, lanes 0-15)
    const int bl = lane & 15;
    const int b_rowbase = (wq * 32 + (bl & 7)) * 128 + ((bl >> 3) * 16);

    // my two hidden units
    const int huA = wq * 8 + lq;
    const int huB = huA + 4;

    // ---- L1 biases for my 8 column slots (new mapping) ----
    // slot (nt, c): hu = (nt>=2 ? huB : huA), gi = (nt&1)*2 + c
    float bias1[4][2];
#pragma unroll
    for (int nt = 0; nt < 4; nt++)
#pragma unroll
        for (int cc = 0; cc < 2; cc++) {
            int hu = (nt >> 1) ? huB : huA;
            int gi = (nt & 1) * 2 + cc;
            bias1[nt][cc] = bih1[gi * HDIM + hu] + bhh1[gi * HDIM + hu];
        }

    // cell states: [pair(hu) * 2 + rowhalf], pair 0 = huA, 1 = huB
    float cs0[8], cs1[8];
#pragma unroll
    for (int i = 0; i < 8; i++) { cs0[i] = 0.0f; cs1[i] = 0.0f; }

    // zx base: row = cta*32 + wm*16 + lrow, col = huA*4 (halves)
    const __half* zbase = g_zx +
        ((size_t)(blockIdx.x * MROWS + wm * 16 + lrow) * GDIM + huA * 4);
    const int bid = 1 + wm;              // per-row-half barrier (256 threads)

    int pp = 0;

#define LDA(aa, HB, kt)                                                         \
    do {                                                                        \
        uint32_t off = (uint32_t)((wm * 16 + a_rowpart) * 128 +                 \
                                  (kt) * 32 + a_colpart);                       \
        ldsm4(aa, (HB) + swz(off));                                             \
    } while (0)

#define GEMM_S(HB, WB, D)                                                       \
    do {                                                                        \
        _Pragma("unroll")                                                       \
        for (int kt = 0; kt < 4; kt++) {                                        \
            uint32_t a[4];                                                      \
            LDA(a, HB, kt);                                                     \
            _Pragma("unroll")                                                   \
            for (int nt = 0; nt < 4; nt++) {                                    \
                uint32_t b[2];                                                  \
                uint32_t boff = (uint32_t)(b_rowbase + nt * 1024 + kt * 32);    \
                ldsm2(b, (WB) + swz(boff));                                     \
                mma16816(D[nt], a, b);                                          \
            }                                                                   \
        }                                                                       \
    } while (0)

    // Thread-local cell update: pair p in {0,1} -> d[2p]=(i,f), d[2p+1]=(g,o)
    // rowhalf hf in {0,1} -> slots 2hf, 2hf+1 ; row = wm*16 + lrow + 8*hf
#define CELL(CS, HW, D)                                                         \
    do {                                                                        \
        _Pragma("unroll")                                                       \
        for (int p = 0; p < 2; p++) {                                           \
            int hk = p ? huB : huA;                                             \
            _Pragma("unroll")                                                   \
            for (int hf = 0; hf < 2; hf++) {                                    \
                float iv = sigm(D[2 * p][2 * hf + 0]);                          \
                float fv = sigm(D[2 * p][2 * hf + 1]);                          \
                float gv = tanh_(D[2 * p + 1][2 * hf + 0]);                     \
                float ov = sigm(D[2 * p + 1][2 * hf + 1]);                      \
                float c  = fv * CS[p * 2 + hf] + iv * gv;                       \
                CS[p * 2 + hf] = c;                                             \
                sts_h(HW, wm * 16 + lrow + 8 * hf, hk,                          \
                      __float2half_rn(ov * tanh_(c)));                          \
            }                                                                   \
        }                                                                       \
    } while (0)

#pragma unroll 1
    for (int t = 0; t < TDIM; t++) {
        float d0[4][4], d1[4][4];
        const __half* zt = zbase + (size_t)t * (BDIM * GDIM);

        // zx loads first (latency hidden by L1b GEMM)
        // slot nt needs g_zx halves at col offset (nt>>1)*16 + (nt&1)*2
        uint32_t zr[8];
#pragma unroll
        for (int nt = 0; nt < 4; nt++) {
            int co = (nt >> 1) * 16 + (nt & 1) * 2;
            zr[nt * 2 + 0] = *reinterpret_cast<const uint32_t*>(zt + co);
            zr[nt * 2 + 1] = *reinterpret_cast<const uint32_t*>(
                zt + (size_t)8 * GDIM + co);
        }

        // d1 = bias ; d1 += h1_old @ Whh1  (independent of layer 0)
#pragma unroll
        for (int nt = 0; nt < 4; nt++) {
            d1[nt][0] = bias1[nt][0]; d1[nt][1] = bias1[nt][1];
            d1[nt][2] = bias1[nt][0]; d1[nt][3] = bias1[nt][1];
        }
        GEMM_S(h1base[pp], w1bbase, d1);

        // d0 = zx ; d0 += h0_old @ Whh0
#pragma unroll
        for (int nt = 0; nt < 4; nt++) {
            __half2 za = *reinterpret_cast<const __half2*>(&zr[nt * 2 + 0]);
            __half2 zb = *reinterpret_cast<const __half2*>(&zr[nt * 2 + 1]);
            float2 fa = __half22float2(za);
            float2 fb = __half22float2(zb);
            d0[nt][0] = fa.x; d0[nt][1] = fa.y;
            d0[nt][2] = fb.x; d0[nt][3] = fb.y;
        }
        GEMM_S(h0base[pp], w0base, d0);

        // cell 0 -> h0_new  (thread-local, no shfl)
        CELL(cs0, h0buf[pp ^ 1], d0);
        barn(bid, 256);                 // own row-half only

        // d1 += h0_new @ Wih1 ; cell 1 -> h1_new
        GEMM_S(h0base[pp ^ 1], w1abase, d1);
        CELL(cs1, h1buf[pp ^ 1], d1);
        barn(bid, 256);

        pp ^= 1;
    }

    __syncthreads();

    // ---- final FC on last h1 (now in h1buf[pp]) ----
    if (tid < MROWS) {
        const __half* hf = h1buf[pp];
        float s = bfc[0];
#pragma unroll 8
        for (int k = 0; k < HDIM; k++) {
            int off = tid * 128 + k * 2;
            off ^= (off >> 3) & 0x70;
            s += __half2float(*reinterpret_cast<const __half*>(
                     reinterpret_cast<const char*>(hf) + off)) * Wfc[k];
        }
        out[blockIdx.x * MROWS + tid] = s;
    }
}

// =====================================================================
extern "C" void kernel_launch(void* const* d_in, const int* in_sizes, int n_in,
                              void* d_out, int out_size)
{
    const float* x    = (const float*)d_in[0];
    const float* Wih0 = (const float*)d_in[1];
    const float* Whh0 = (const float*)d_in[2];
    const float* bih0 = (const float*)d_in[3];
    const float* bhh0 = (const float*)d_in[4];
    const float* Wih1 = (const float*)d_in[5];
    const float* Whh1 = (const float*)d_in[6];
    const float* bih1 = (const float*)d_in[7];
    const float* bhh1 = (const float*)d_in[8];
    const float* Wfc  = (const float*)d_in[9];
    const float* bfc  = (const float*)d_in[10];
    float* out = (float*)d_out;

    const int smem_bytes = (3 * 256 * 64 + 4 * 2048) * 2;
    cudaFuncSetAttribute(lstm_kernel,
                         cudaFuncAttributeMaxDynamicSharedMemorySize, smem_bytes);

    dim3 pgrid(TDIM / TB, BDIM / BB);
    prep_kernel<<<pgrid, PNT>>>(x, Wih0, bih0, bhh0);
    lstm_kernel<<<LCTA, NT, smem_bytes>>>(Whh0, Wih1, Whh1, bih1, bhh1,
                                          Wfc, bfc, out);
}

// round 17
// speedup vs baseline: 5.1873x; 1.9711x over previous
#include <cuda_runtime.h>
#include <cuda_fp16.h>
#include <cstdint>
#include <cstddef>

// Problem constants
#define BDIM 4096
#define TDIM 168
#define IDIM 19
#define HDIM 64
#define GDIM 256          // 4*H
#define MROWS 32          // rows per CTA
#define LCTA 128          // lstm CTAs (128*32 = 4096)
#define NT   512          // 16 warps: wq = w&7 (32 cols), wm = w>>3 (16 rows)
#define XW   20           // padded x inner dim (halves) -> 10 uint32

// 27.5 MB scratch: xh[t][b][20] fp16 (x transposed + padded, col 19 = 0)
__device__ __half g_xh[(size_t)TDIM * BDIM * XW];

// ---------------- fast activations (tanh.approx MUFU) ----------------
__device__ __forceinline__ float tanhfast(float x) {
    float y; asm("tanh.approx.f32 %0, %1;" : "=f"(y) : "f"(x)); return y;
}
__device__ __forceinline__ float sigm(float z) {
    return fmaf(0.5f, tanhfast(0.5f * z), 0.5f);
}
__device__ __forceinline__ float tanh_(float z) { return tanhfast(z); }

// ---------------- smem half access with XOR swizzle ------
__device__ __forceinline__ void sts_h(__half* base, int row, int k, __half v) {
    int off = row * 128 + k * 2;
    off ^= (off >> 3) & 0x70;
    *reinterpret_cast<__half*>(reinterpret_cast<char*>(base) + off) = v;
}
__device__ __forceinline__ uint32_t swz(uint32_t off) {
    return off ^ ((off >> 3) & 0x70);
}

// ---------------- mma / ldmatrix ----------------
__device__ __forceinline__ void mma16816(float* d, const uint32_t* a,
                                         const uint32_t* b) {
    asm volatile(
        "mma.sync.aligned.m16n8k16.row.col.f32.f16.f16.f32 "
        "{%0,%1,%2,%3},{%4,%5,%6,%7},{%8,%9},{%0,%1,%2,%3};"
        : "+f"(d[0]), "+f"(d[1]), "+f"(d[2]), "+f"(d[3])
        : "r"(a[0]), "r"(a[1]), "r"(a[2]), "r"(a[3]), "r"(b[0]), "r"(b[1]));
}
__device__ __forceinline__ void ldsm4(uint32_t* a, uint32_t addr) {
    asm volatile(
        "ldmatrix.sync.aligned.m8n8.x4.shared.b16 {%0,%1,%2,%3}, [%4];"
        : "=r"(a[0]), "=r"(a[1]), "=r"(a[2]), "=r"(a[3]) : "r"(addr));
}
__device__ __forceinline__ void ldsm2(uint32_t* b, uint32_t addr) {
    asm volatile(
        "ldmatrix.sync.aligned.m8n8.x2.shared.b16 {%0,%1}, [%2];"
        : "=r"(b[0]), "=r"(b[1]) : "r"(addr));
}

// ---------------- named barrier ----------------
__device__ __forceinline__ void barn(int id, int cnt) {
    asm volatile("bar.sync %0, %1;" :: "r"(id), "r"(cnt) : "memory");
}

// smem weight-column permutation: column n -> torch gate row g.
// Thread lq's col-pairs in n-tiles (0,1)/(2,3) hold gates (i,f|g,o) of
// hu_A / hu_B -> fully thread-local cell update.
__device__ __forceinline__ int colmap(int n) {
    int wq_ = n >> 5, r = n & 31;
    int nt = r >> 3, lq_ = (r & 7) >> 1, c = r & 1;
    int hu = wq_ * 8 + (nt >> 1) * 4 + lq_;
    int gi = (nt & 1) * 2 + c;
    return gi * HDIM + hu;
}

// =====================================================================
// Transpose kernel: x [b][t][19] f32  ->  g_xh [t][b][20] f16 (col 19 = 0)
// Block: 32 b x 8 t, 256 threads. Reads contiguous 152-float runs per b,
// writes contiguous 320-uint32 runs per t.
// =====================================================================
#define XT_TB 8
#define XT_BB 32
__global__ void __launch_bounds__(256) xpose_kernel(const float* __restrict__ x)
{
    __shared__ __half sX[XT_TB][XT_BB][XW];
    const int tid = threadIdx.x;
    const int t0 = blockIdx.x * XT_TB;
    const int b0 = blockIdx.y * XT_BB;

    // zero pad column
    if (tid < XT_TB * XT_BB) sX[tid >> 5][tid & 31][IDIM] = __half(0.0f);

    // read: per b, 152 consecutive floats (8 t x 19 i)
    for (int idx = tid; idx < XT_BB * (XT_TB * IDIM); idx += 256) {
        int b = idx / (XT_TB * IDIM);
        int r = idx % (XT_TB * IDIM);
        int t = r / IDIM, i = r % IDIM;
        sX[t][b][i] = __float2half_rn(
            x[((size_t)(b0 + b) * TDIM + t0) * IDIM + r]);
    }
    __syncthreads();

    // write: per t, 32 b x 10 uint32 contiguous
    uint32_t* dst = reinterpret_cast<uint32_t*>(g_xh);
    for (int idx = tid; idx < XT_TB * XT_BB * (XW / 2); idx += 256) {
        int u = idx % (XW / 2);
        int b = (idx / (XW / 2)) & 31;
        int t = idx / (XT_BB * (XW / 2));
        dst[((size_t)(t0 + t) * BDIM + (b0 + b)) * (XW / 2) + u] =
            reinterpret_cast<uint32_t*>(&sX[t][b][0])[u];
    }
}

// =====================================================================
// LSTM kernel: 128 CTAs x 512 threads (16 warps), fp16 HMMA.
// Warp (wq, wm): cols [32wq,32wq+32), rows [16wm,16wm+16).
// R15: zx GEMM fused in-loop (x tile staged per step), tanh.approx MUFU.
// =====================================================================
__global__ void __launch_bounds__(NT, 1) lstm_kernel(
    const float* __restrict__ Wih0,
    const float* __restrict__ Whh0,
    const float* __restrict__ bih0,
    const float* __restrict__ bhh0,
    const float* __restrict__ Wih1,
    const float* __restrict__ Whh1,
    const float* __restrict__ bih1,
    const float* __restrict__ bhh1,
    const float* __restrict__ Wfc,
    const float* __restrict__ bfc,
    float* __restrict__ out)
{
    extern __shared__ __align__(16) __half smem[];
    __half* sW0  = smem;                 // Whh0: 256 x 64 halves (32 KB)
    __half* sW1a = sW0 + 256 * 64;       // Wih1 (32 KB)
    __half* sW1b = sW1a + 256 * 64;      // Whh1 (32 KB)
    __half* sWx  = sW1b + 256 * 64;      // Wih0 k-padded to 64 (32 KB)
    __half* h0buf[2] = { sWx + 256 * 64,        sWx + 256 * 64 + 2048 };
    __half* h1buf[2] = { sWx + 256 * 64 + 4096, sWx + 256 * 64 + 6144 };
    __half* xbuf[2]  = { sWx + 256 * 64 + 8192, sWx + 256 * 64 + 10240 };

    const int tid  = threadIdx.x;
    const int w    = tid >> 5;
    const int wq   = w & 7;              // column group
    const int wm   = w >> 3;             // row half
    const int lane = tid & 31;
    const int lrow = lane >> 2;          // 0..7
    const int lq   = lane & 3;           // 0..3
    const int htid = tid & 255;          // index within row-half

    // ---- stage weights fp32 -> fp16 with the thread-local permutation ----
    for (int idx = tid; idx < 256 * 64; idx += NT) {
        int n = idx >> 6, k = idx & 63;
        int g = colmap(n);
        sts_h(sW0,  n, k, __float2half_rn(Whh0[g * HDIM + k]));
        sts_h(sW1a, n, k, __float2half_rn(Wih1[g * HDIM + k]));
        sts_h(sW1b, n, k, __float2half_rn(Whh1[g * HDIM + k]));
        sts_h(sWx,  n, k, (k < IDIM) ? __float2half_rn(Wih0[g * IDIM + k])
                                     : __half(0.0f));
    }
    for (int idx = tid; idx < 2048; idx += NT) {
        h0buf[0][idx] = __half(0.0f); h0buf[1][idx] = __half(0.0f);
        h1buf[0][idx] = __half(0.0f); h1buf[1][idx] = __half(0.0f);
        xbuf[0][idx]  = __half(0.0f); xbuf[1][idx]  = __half(0.0f);
    }
    __syncthreads();

    const uint32_t h0base[2] = {
        (uint32_t)__cvta_generic_to_shared(h0buf[0]),
        (uint32_t)__cvta_generic_to_shared(h0buf[1]) };
    const uint32_t h1base[2] = {
        (uint32_t)__cvta_generic_to_shared(h1buf[0]),
        (uint32_t)__cvta_generic_to_shared(h1buf[1]) };
    const uint32_t xbase[2] = {
        (uint32_t)__cvta_generic_to_shared(xbuf[0]),
        (uint32_t)__cvta_generic_to_shared(xbuf[1]) };
    const uint32_t w0base  = (uint32_t)__cvta_generic_to_shared(sW0);
    const uint32_t w1abase = (uint32_t)__cvta_generic_to_shared(sW1a);
    const uint32_t w1bbase = (uint32_t)__cvta_generic_to_shared(sW1b);
    const uint32_t wxbase  = (uint32_t)__cvta_generic_to_shared(sWx);

    // A-frag lane offsets (ldmatrix.x4 over 16 rows x 16 cols)
    const int a_rowpart = ((lane >> 3) & 1) * 8 + (lane & 7);
    const int a_colpart = (lane >> 4) * 16;        // bytes
    // B-frag lane offsets (ldmatrix.x2, lanes 0-15)
    const int bl = lane & 15;
    const int b_rowbase = (wq * 32 + (bl & 7)) * 128 + ((bl >> 3) * 16);

    // my two hidden units
    const int huA = wq * 8 + lq;
    const int huB = huA + 4;

    // ---- L0/L1 biases for my 8 column slots ----
    float bias0[4][2], bias1[4][2];
#pragma unroll
    for (int nt = 0; nt < 4; nt++)
#pragma unroll
        for (int cc = 0; cc < 2; cc++) {
            int hu = (nt >> 1) ? huB : huA;
            int gi = (nt & 1) * 2 + cc;
            bias0[nt][cc] = bih0[gi * HDIM + hu] + bhh0[gi * HDIM + hu];
            bias1[nt][cc] = bih1[gi * HDIM + hu] + bhh1[gi * HDIM + hu];
        }

    // cell states: [pair(hu) * 2 + rowhalf]
    float cs0[8], cs1[8];
#pragma unroll
    for (int i = 0; i < 8; i++) { cs0[i] = 0.0f; cs1[i] = 0.0f; }

    // ---- x staging setup: threads htid<160 of each half stage 1 uint32 ----
    const bool doStage = (htid < 160);
    const int  st_row  = wm * 16 + htid / 10;          // row in CTA
    const int  st_u    = htid % 10;
    const uint32_t* xg = reinterpret_cast<const uint32_t*>(g_xh) +
        ((size_t)(blockIdx.x * MROWS + st_row)) * (XW / 2) + st_u;
    // swizzled smem byte offset for this thread's x slot
    uint32_t st_off = swz((uint32_t)(st_row * 128 + st_u * 4));

    const int bid = 1 + wm;              // per-row-half barrier (256 threads)
    int pp = 0;

    // stage x_0 into xbuf[0]
    if (doStage) {
        uint32_t v = xg[0];
        *reinterpret_cast<uint32_t*>(
            reinterpret_cast<char*>(xbuf[0]) + st_off) = v;
    }
    __syncthreads();

#define LDA(aa, HB, kt)                                                         \
    do {                                                                        \
        uint32_t off = (uint32_t)((wm * 16 + a_rowpart) * 128 +                 \
                                  (kt) * 32 + a_colpart);                       \
        ldsm4(aa, (HB) + swz(off));                                             \
    } while (0)

#define GEMM_SN(HB, WB, D, KTN)                                                 \
    do {                                                                        \
        _Pragma("unroll")                                                       \
        for (int kt = 0; kt < (KTN); kt++) {                                    \
            uint32_t a[4];                                                      \
            LDA(a, HB, kt);                                                     \
            _Pragma("unroll")                                                   \
            for (int nt = 0; nt < 4; nt++) {                                    \
                uint32_t b[2];                                                  \
                uint32_t boff = (uint32_t)(b_rowbase + nt * 1024 + kt * 32);    \
                ldsm2(b, (WB) + swz(boff));                                     \
                mma16816(D[nt], a, b);                                          \
            }                                                                   \
        }                                                                       \
    } while (0)

    // Thread-local cell update (no shfl): pair p -> d[2p]=(i,f), d[2p+1]=(g,o)
#define CELL(CS, HW, D)                                                         \
    do {                                                                        \
        _Pragma("unroll")                                                       \
        for (int p = 0; p < 2; p++) {                                           \
            int hk = p ? huB : huA;                                             \
            _Pragma("unroll")                                                   \
            for (int hf = 0; hf < 2; hf++) {                                    \
                float iv = sigm(D[2 * p][2 * hf + 0]);                          \
                float fv = sigm(D[2 * p][2 * hf + 1]);                          \
                float gv = tanh_(D[2 * p + 1][2 * hf + 0]);                     \
                float ov = sigm(D[2 * p + 1][2 * hf + 1]);                      \
                float c  = fv * CS[p * 2 + hf] + iv * gv;                       \
                CS[p * 2 + hf] = c;                                             \
                sts_h(HW, wm * 16 + lrow + 8 * hf, hk,                          \
                      __float2half_rn(ov * tanh_(c)));                          \
            }                                                                   \
        }                                                                       \
    } while (0)

#pragma unroll 1
    for (int t = 0; t < TDIM; t++) {
        float d0[4][4], d1[4][4];

        // issue next-step x load early (consumed after the GEMMs)
        uint32_t xv = 0;
        const bool st = doStage && (t + 1 < TDIM);
        if (st) xv = xg[(size_t)(t + 1) * (BDIM * (XW / 2))];

        // d1 = bias1 ; d1 += h1_old @ Whh1  (independent of layer 0)
#pragma unroll
        for (int nt = 0; nt < 4; nt++) {
            d1[nt][0] = bias1[nt][0]; d1[nt][1] = bias1[nt][1];
            d1[nt][2] = bias1[nt][0]; d1[nt][3] = bias1[nt][1];
        }
        GEMM_SN(h1base[pp], w1bbase, d1, 4);

        // d0 = bias0 ; d0 += x_t @ Wih0 (k=32) ; d0 += h0_old @ Whh0
#pragma unroll
        for (int nt = 0; nt < 4; nt++) {
            d0[nt][0] = bias0[nt][0]; d0[nt][1] = bias0[nt][1];
            d0[nt][2] = bias0[nt][0]; d0[nt][3] = bias0[nt][1];
        }
        GEMM_SN(xbase[pp], wxbase, d0, 2);
        GEMM_SN(h0base[pp], w0base, d0, 4);

        // store next x tile (own rows; read only after next barrier)
        if (st)
            *reinterpret_cast<uint32_t*>(
                reinterpret_cast<char*>(xbuf[pp ^ 1]) + st_off) = xv;

        // cell 0 -> h0_new  (thread-local)
        CELL(cs0, h0buf[pp ^ 1], d0);
        barn(bid, 256);                 // own row-half only

        // d1 += h0_new @ Wih1 ; cell 1 -> h1_new
        GEMM_SN(h0base[pp ^ 1], w1abase, d1, 4);
        CELL(cs1, h1buf[pp ^ 1], d1);
        barn(bid, 256);

        pp ^= 1;
    }

    __syncthreads();

    // ---- final FC on last h1 (now in h1buf[pp]) ----
    if (tid < MROWS) {
        const __half* hf = h1buf[pp];
        float s = bfc[0];
#pragma unroll 8
        for (int k = 0; k < HDIM; k++) {
            int off = tid * 128 + k * 2;
            off ^= (off >> 3) & 0x70;
            s += __half2float(*reinterpret_cast<const __half*>(
                     reinterpret_cast<const char*>(hf) + off)) * Wfc[k];
        }
        out[blockIdx.x * MROWS + tid] = s;
    }
}

// =====================================================================
extern "C" void kernel_launch(void* const* d_in, const int* in_sizes, int n_in,
                              void* d_out, int out_size)
{
    const float* x    = (const float*)d_in[0];
    const float* Wih0 = (const float*)d_in[1];
    const float* Whh0 = (const float*)d_in[2];
    const float* bih0 = (const float*)d_in[3];
    const float* bhh0 = (const float*)d_in[4];
    const float* Wih1 = (const float*)d_in[5];
    const float* Whh1 = (const float*)d_in[6];
    const float* bih1 = (const float*)d_in[7];
    const float* bhh1 = (const float*)d_in[8];
    const float* Wfc  = (const float*)d_in[9];
    const float* bfc  = (const float*)d_in[10];
    float* out = (float*)d_out;

    // 4 weight tiles (128 KB) + h bufs (8 KB) + x bufs (8 KB) = 144 KB
    const int smem_bytes = (4 * 256 * 64 + 6 * 2048) * 2;
    cudaFuncSetAttribute(lstm_kernel,
                         cudaFuncAttributeMaxDynamicSharedMemorySize, smem_bytes);

    dim3 xgrid(TDIM / XT_TB, BDIM / XT_BB);
    xpose_kernel<<<xgrid, 256>>>(x);
    lstm_kernel<<<LCTA, NT, smem_bytes>>>(Wih0, Whh0, bih0, bhh0,
                                          Wih1, Whh1, bih1, bhh1,
                                          Wfc, bfc, out);
}